// round 1
// baseline (speedup 1.0000x reference)
#include <cuda_runtime.h>
#include <cstddef>

// Problem constants
static constexpr int BATCH  = 4;
static constexpr int SEQ    = 2048;
static constexpr int DMODEL = 1024;
static constexpr int NHEAD  = 16;
static constexpr int DHEAD  = 64;
static constexpr int MROWS  = BATCH * SEQ;   // 8192

// Scratch (device globals — no allocations allowed)
__device__ float g_q[MROWS * DMODEL];
__device__ float g_k[MROWS * DMODEL];
__device__ float g_v[MROWS * DMODEL];
__device__ float g_att[MROWS * DMODEL];

// ---------------------------------------------------------------------------
// SGEMM: C[M,N] = A[M,K] * B[K,N], all row-major, fp32.
// 128x128 block tile, BK=8, 256 threads, 8x8 micro-tile per thread.
// ---------------------------------------------------------------------------
__global__ __launch_bounds__(256) void sgemm128(
    const float* __restrict__ A, const float* __restrict__ B,
    float* __restrict__ C, int M, int N, int K)
{
    __shared__ float As[8][128];   // transposed A tile: As[k][m]
    __shared__ float Bs[8][128];   // Bs[k][n]

    const int tid = threadIdx.x;
    const int tx = tid & 15;         // 0..15 -> n
    const int ty = tid >> 4;         // 0..15 -> m
    const int bm0 = blockIdx.y * 128;
    const int bn0 = blockIdx.x * 128;

    // global load assignments
    const int ar = tid >> 1;               // 0..127
    const int ac = (tid & 1) * 4;          // 0 or 4
    const int br = tid >> 5;               // 0..7
    const int bc = (tid & 31) * 4;         // 0..124

    const float* Aptr = A + (size_t)(bm0 + ar) * K + ac;
    const float* Bptr = B + (size_t)br * N + bn0 + bc;

    float acc[8][8];
    #pragma unroll
    for (int i = 0; i < 8; i++)
        #pragma unroll
        for (int j = 0; j < 8; j++) acc[i][j] = 0.0f;

    for (int k0 = 0; k0 < K; k0 += 8) {
        float4 a4 = *(const float4*)Aptr;  Aptr += 8;
        float4 b4 = *(const float4*)Bptr;  Bptr += (size_t)8 * N;

        __syncthreads();   // previous tile fully consumed
        As[ac + 0][ar] = a4.x;
        As[ac + 1][ar] = a4.y;
        As[ac + 2][ar] = a4.z;
        As[ac + 3][ar] = a4.w;
        *(float4*)&Bs[br][bc] = b4;
        __syncthreads();

        #pragma unroll
        for (int k = 0; k < 8; k++) {
            float ra[8], rb[8];
            float4 a0 = *(const float4*)&As[k][ty * 8];
            float4 a1 = *(const float4*)&As[k][ty * 8 + 4];
            float4 b0 = *(const float4*)&Bs[k][tx * 8];
            float4 b1 = *(const float4*)&Bs[k][tx * 8 + 4];
            ra[0]=a0.x; ra[1]=a0.y; ra[2]=a0.z; ra[3]=a0.w;
            ra[4]=a1.x; ra[5]=a1.y; ra[6]=a1.z; ra[7]=a1.w;
            rb[0]=b0.x; rb[1]=b0.y; rb[2]=b0.z; rb[3]=b0.w;
            rb[4]=b1.x; rb[5]=b1.y; rb[6]=b1.z; rb[7]=b1.w;
            #pragma unroll
            for (int i = 0; i < 8; i++)
                #pragma unroll
                for (int j = 0; j < 8; j++)
                    acc[i][j] += ra[i] * rb[j];
        }
    }

    // epilogue: vectorized stores
    #pragma unroll
    for (int i = 0; i < 8; i++) {
        float* cp = C + (size_t)(bm0 + ty * 8 + i) * N + bn0 + tx * 8;
        float4 v0, v1;
        v0.x = acc[i][0]; v0.y = acc[i][1]; v0.z = acc[i][2]; v0.w = acc[i][3];
        v1.x = acc[i][4]; v1.y = acc[i][5]; v1.z = acc[i][6]; v1.w = acc[i][7];
        *(float4*)cp       = v0;
        *(float4*)(cp + 4) = v1;
    }
}

// ---------------------------------------------------------------------------
// Flash attention (causal, fp32). One query row per thread; 128 rows per CTA.
// K/V tiles of 64 keys staged in smem (broadcast reads). Online softmax with
// per-row score vector parked in smem at stride 65 (conflict-free).
// ---------------------------------------------------------------------------
__global__ __launch_bounds__(128) void flash_attn(
    const float* __restrict__ Qg, const float* __restrict__ Kg,
    const float* __restrict__ Vg, float* __restrict__ Og)
{
    extern __shared__ float sm[];
    float* Ks = sm;                 // 64*64
    float* Vs = sm + 64 * 64;       // 64*64
    float* Ss = sm + 2 * 64 * 64;   // 128*65

    const int tid = threadIdx.x;
    const int b = blockIdx.z;
    const int h = blockIdx.y;
    const int q0 = blockIdx.x * 128;
    const int row = q0 + tid;

    const float scale = 0.125f;  // 1/sqrt(64)

    // load + pre-scale this thread's query row into registers
    float q[DHEAD];
    {
        const float* qp = Qg + ((size_t)(b * SEQ + row)) * DMODEL + h * DHEAD;
        #pragma unroll
        for (int d = 0; d < DHEAD; d += 4) {
            float4 v = *(const float4*)(qp + d);
            q[d + 0] = v.x * scale;
            q[d + 1] = v.y * scale;
            q[d + 2] = v.z * scale;
            q[d + 3] = v.w * scale;
        }
    }

    float o[DHEAD];
    #pragma unroll
    for (int d = 0; d < DHEAD; d++) o[d] = 0.0f;
    float m = -1e30f, l = 0.0f;

    const int ntiles = q0 / 64 + 2;   // covers keys 0 .. q0+127

    for (int t = 0; t < ntiles; t++) {
        const int k0 = t * 64;

        // cooperative K/V tile load: 64 keys x 64 dims each
        {
            const float* kp = Kg + ((size_t)(b * SEQ + k0)) * DMODEL + h * DHEAD;
            const float* vp = Vg + ((size_t)(b * SEQ + k0)) * DMODEL + h * DHEAD;
            #pragma unroll
            for (int i = tid; i < 1024; i += 128) {
                int r = i >> 4;
                int c = (i & 15) << 2;
                *(float4*)&Ks[r * 64 + c] = *(const float4*)(kp + (size_t)r * DMODEL + c);
                *(float4*)&Vs[r * 64 + c] = *(const float4*)(vp + (size_t)r * DMODEL + c);
            }
        }
        __syncthreads();

        // scores for this thread's row vs 64 keys
        float mn = m;
        const bool need_mask = (k0 + 63 > row);
        #pragma unroll 4
        for (int j = 0; j < 64; j++) {
            float s = 0.0f;
            #pragma unroll
            for (int d = 0; d < DHEAD; d++)
                s += q[d] * Ks[j * 64 + d];
            if (need_mask && (k0 + j > row)) s = -1e30f;
            Ss[tid * 65 + j] = s;
            mn = fmaxf(mn, s);
        }

        // online softmax rescale
        const float corr = __expf(m - mn);
        l *= corr;
        #pragma unroll
        for (int d = 0; d < DHEAD; d++) o[d] *= corr;

        // accumulate P*V
        for (int j = 0; j < 64; j++) {
            float p = __expf(Ss[tid * 65 + j] - mn);
            l += p;
            #pragma unroll
            for (int d = 0; d < DHEAD; d++)
                o[d] += p * Vs[j * 64 + d];
        }
        m = mn;
        __syncthreads();   // before next tile overwrites Ks/Vs
    }

    const float inv = 1.0f / l;
    float* op = Og + ((size_t)(b * SEQ + row)) * DMODEL + h * DHEAD;
    #pragma unroll
    for (int d = 0; d < DHEAD; d += 4) {
        float4 v;
        v.x = o[d + 0] * inv;
        v.y = o[d + 1] * inv;
        v.z = o[d + 2] * inv;
        v.w = o[d + 3] * inv;
        *(float4*)(op + d) = v;
    }
}

// ---------------------------------------------------------------------------
// Launch
// ---------------------------------------------------------------------------
extern "C" void kernel_launch(void* const* d_in, const int* in_sizes, int n_in,
                              void* d_out, int out_size)
{
    const float* x  = (const float*)d_in[0];
    const float* wq = (const float*)d_in[1];
    const float* wk = (const float*)d_in[2];
    const float* wv = (const float*)d_in[3];
    const float* wo = (const float*)d_in[4];
    float* out = (float*)d_out;

    float *qb, *kb, *vb, *ab;
    cudaGetSymbolAddress((void**)&qb, g_q);
    cudaGetSymbolAddress((void**)&kb, g_k);
    cudaGetSymbolAddress((void**)&vb, g_v);
    cudaGetSymbolAddress((void**)&ab, g_att);

    dim3 gg(DMODEL / 128, MROWS / 128);   // (8, 64)

    sgemm128<<<gg, 256>>>(x, wq, qb, MROWS, DMODEL, DMODEL);
    sgemm128<<<gg, 256>>>(x, wk, kb, MROWS, DMODEL, DMODEL);
    sgemm128<<<gg, 256>>>(x, wv, vb, MROWS, DMODEL, DMODEL);

    const int smem = (2 * 64 * 64 + 128 * 65) * (int)sizeof(float); // 66048 B
    cudaFuncSetAttribute(flash_attn, cudaFuncAttributeMaxDynamicSharedMemorySize, smem);
    dim3 fg(SEQ / 128, NHEAD, BATCH);     // (16, 16, 4)
    flash_attn<<<fg, 128, smem>>>(qb, kb, vb, ab);

    sgemm128<<<gg, 256>>>(ab, wo, out, MROWS, DMODEL, DMODEL);
}

// round 2
// speedup vs baseline: 1.1661x; 1.1661x over previous
#include <cuda_runtime.h>
#include <mma.h>
#include <cstddef>

using namespace nvcuda;

// Problem constants
static constexpr int BATCH  = 4;
static constexpr int SEQ    = 2048;
static constexpr int DMODEL = 1024;
static constexpr int NHEAD  = 16;
static constexpr int DHEAD  = 64;
static constexpr int MROWS  = BATCH * SEQ;   // 8192

// Scratch (device globals — no allocations allowed)
__device__ float g_q[MROWS * DMODEL];
__device__ float g_k[MROWS * DMODEL];
__device__ float g_v[MROWS * DMODEL];
__device__ float g_att[MROWS * DMODEL];

__device__ __forceinline__ float t32(float x) { return wmma::__float_to_tf32(x); }

// ---------------------------------------------------------------------------
// TF32 GEMM: C[M,N] = A[M,K] * B[K,N], row-major fp32 in/out.
// 128x128x32 block tile, 256 threads = 8 warps, warp tile 64x32,
// wmma m16n16k8 tf32 with fp32 accumulate. Inputs tf32-rounded (RN) in smem.
// ---------------------------------------------------------------------------
__global__ __launch_bounds__(256) void gemm_tf32(
    const float* __restrict__ A, const float* __restrict__ B,
    float* __restrict__ C, int M, int N, int K)
{
    __shared__ float As[128][36];   // [m][k], pad 4
    __shared__ float Bs[32][136];   // [k][n], pad 8

    const int tid = threadIdx.x;
    const int wid = tid >> 5;
    const int wm = (wid & 1) * 64;      // warp row offset in tile
    const int wn = (wid >> 1) * 32;     // warp col offset in tile
    const long bm0 = (long)blockIdx.y * 128;
    const long bn0 = (long)blockIdx.x * 128;

    wmma::fragment<wmma::accumulator, 16, 16, 8, float> acc[4][2];
    #pragma unroll
    for (int i = 0; i < 4; i++)
        #pragma unroll
        for (int j = 0; j < 2; j++)
            wmma::fill_fragment(acc[i][j], 0.0f);

    for (int k0 = 0; k0 < K; k0 += 32) {
        __syncthreads();   // previous tile fully consumed
        // A tile 128x32: 1024 float4 over 256 threads
        #pragma unroll
        for (int r = 0; r < 4; r++) {
            int idx = tid + r * 256;
            int row = idx >> 3, c = (idx & 7) << 2;
            float4 v = *(const float4*)(A + (bm0 + row) * (long)K + k0 + c);
            As[row][c + 0] = t32(v.x);
            As[row][c + 1] = t32(v.y);
            As[row][c + 2] = t32(v.z);
            As[row][c + 3] = t32(v.w);
        }
        // B tile 32x128
        #pragma unroll
        for (int r = 0; r < 4; r++) {
            int idx = tid + r * 256;
            int row = idx >> 5, c = (idx & 31) << 2;
            float4 v = *(const float4*)(B + (long)(k0 + row) * N + bn0 + c);
            Bs[row][c + 0] = t32(v.x);
            Bs[row][c + 1] = t32(v.y);
            Bs[row][c + 2] = t32(v.z);
            Bs[row][c + 3] = t32(v.w);
        }
        __syncthreads();

        #pragma unroll
        for (int kk = 0; kk < 32; kk += 8) {
            wmma::fragment<wmma::matrix_a, 16, 16, 8, wmma::precision::tf32, wmma::row_major> af[4];
            wmma::fragment<wmma::matrix_b, 16, 16, 8, wmma::precision::tf32, wmma::row_major> bf[2];
            #pragma unroll
            for (int i = 0; i < 4; i++)
                wmma::load_matrix_sync(af[i], &As[wm + i * 16][kk], 36);
            #pragma unroll
            for (int j = 0; j < 2; j++)
                wmma::load_matrix_sync(bf[j], &Bs[kk][wn + j * 16], 136);
            #pragma unroll
            for (int i = 0; i < 4; i++)
                #pragma unroll
                for (int j = 0; j < 2; j++)
                    wmma::mma_sync(acc[i][j], af[i], bf[j], acc[i][j]);
        }
    }

    #pragma unroll
    for (int i = 0; i < 4; i++)
        #pragma unroll
        for (int j = 0; j < 2; j++)
            wmma::store_matrix_sync(C + (bm0 + wm + i * 16) * (long)N + bn0 + wn + j * 16,
                                    acc[i][j], N, wmma::mem_row_major);
}

// ---------------------------------------------------------------------------
// Flash attention (causal), TF32 tensor-core QK^T and PV, fp32 softmax/accum.
// One (b, h, 64-query tile) per CTA, 256 threads = 8 warps.
// S tile 64x64 via wmma -> smem; softmax 4 threads/row with shfl reduction;
// P rounded to tf32 in place; O lives in smem, updated via accumulator
// fragment load/mma/store (each warp owns 2 disjoint 16x16 output tiles).
// ---------------------------------------------------------------------------
__global__ __launch_bounds__(256) void flash_tf32(
    const float* __restrict__ Qg, const float* __restrict__ Kg,
    const float* __restrict__ Vg, float* __restrict__ Og)
{
    extern __shared__ float sm[];
    float* Qs   = sm;               // [64][68]
    float* Ks   = Qs + 64 * 68;     // [64][68]
    float* Vs   = Ks + 64 * 68;     // [64][68]
    float* Oa   = Vs + 64 * 68;     // [64][68]
    float* Ss   = Oa + 64 * 68;     // [64][72]  scores, then P
    float* crow = Ss + 64 * 72;     // [64]
    float* lrow = crow + 64;        // [64]

    const int tid = threadIdx.x;
    const int wid = tid >> 5;
    const int b = blockIdx.z, h = blockIdx.y;
    const int q0 = blockIdx.x * 64;

    // Load Q tile (pre-scaled by 1/8, tf32-rounded) and zero O accumulator.
    #pragma unroll
    for (int r = 0; r < 4; r++) {
        int idx = tid + r * 256;
        int row = idx >> 4, c = (idx & 15) << 2;
        float4 v = *(const float4*)(Qg + ((long)(b * SEQ + q0 + row)) * DMODEL + h * DHEAD + c);
        Qs[row * 68 + c + 0] = t32(v.x * 0.125f);
        Qs[row * 68 + c + 1] = t32(v.y * 0.125f);
        Qs[row * 68 + c + 2] = t32(v.z * 0.125f);
        Qs[row * 68 + c + 3] = t32(v.w * 0.125f);
    }
    #pragma unroll
    for (int i = 0; i < 16; i++) {
        int idx = tid + i * 256;
        Oa[(idx >> 6) * 68 + (idx & 63)] = 0.0f;
    }

    const int row4 = tid >> 2;  // softmax row owned (4 threads per row)
    const int sub  = tid & 3;
    float m = -1e30f, l = 0.0f;

    const int ntiles = blockIdx.x + 1;   // causal: keys up to q0+63
    for (int t = 0; t < ntiles; t++) {
        const int k0 = t * 64;
        __syncthreads();   // prior-iter consumers of Ks/Vs/Ss done; first iter: Qs/Oa visible

        // Load K/V tile (tf32-rounded)
        #pragma unroll
        for (int r = 0; r < 4; r++) {
            int idx = tid + r * 256;
            int row = idx >> 4, c = (idx & 15) << 2;
            long base = ((long)(b * SEQ + k0 + row)) * DMODEL + h * DHEAD + c;
            float4 kv = *(const float4*)(Kg + base);
            Ks[row * 68 + c + 0] = t32(kv.x);
            Ks[row * 68 + c + 1] = t32(kv.y);
            Ks[row * 68 + c + 2] = t32(kv.z);
            Ks[row * 68 + c + 3] = t32(kv.w);
            float4 vv = *(const float4*)(Vg + base);
            Vs[row * 68 + c + 0] = t32(vv.x);
            Vs[row * 68 + c + 1] = t32(vv.y);
            Vs[row * 68 + c + 2] = t32(vv.z);
            Vs[row * 68 + c + 3] = t32(vv.w);
        }
        __syncthreads();

        // S = Q * K^T  (16 output tiles of 16x16, 2 per warp)
        #pragma unroll
        for (int tt = 0; tt < 2; tt++) {
            int tile = wid * 2 + tt;
            int tm = tile >> 2, tn = tile & 3;
            wmma::fragment<wmma::accumulator, 16, 16, 8, float> sacc;
            wmma::fill_fragment(sacc, 0.0f);
            #pragma unroll
            for (int kk = 0; kk < 64; kk += 8) {
                wmma::fragment<wmma::matrix_a, 16, 16, 8, wmma::precision::tf32, wmma::row_major> qa;
                wmma::fragment<wmma::matrix_b, 16, 16, 8, wmma::precision::tf32, wmma::col_major> kb;
                wmma::load_matrix_sync(qa, &Qs[tm * 16 * 68 + kk], 68);
                wmma::load_matrix_sync(kb, &Ks[tn * 16 * 68 + kk], 68);
                wmma::mma_sync(sacc, qa, kb, sacc);
            }
            wmma::store_matrix_sync(&Ss[tm * 16 * 72 + tn * 16], sacc, 72, wmma::mem_row_major);
        }
        __syncthreads();

        // Online softmax: 4 threads per row, 16 cols each.
        {
            const int limit = (t == ntiles - 1) ? (q0 + row4 - k0) : 63;
            float mloc = -1e30f;
            #pragma unroll
            for (int jj = 0; jj < 16; jj++) {
                int j = sub * 16 + jj;
                float s = (j <= limit) ? Ss[row4 * 72 + j] : -1e30f;
                mloc = fmaxf(mloc, s);
            }
            mloc = fmaxf(mloc, __shfl_xor_sync(0xffffffffu, mloc, 1));
            mloc = fmaxf(mloc, __shfl_xor_sync(0xffffffffu, mloc, 2));
            float mnew = fmaxf(m, mloc);
            float corr = __expf(m - mnew);
            float sum = 0.0f;
            #pragma unroll
            for (int jj = 0; jj < 16; jj++) {
                int j = sub * 16 + jj;
                float p = (j <= limit) ? __expf(Ss[row4 * 72 + j] - mnew) : 0.0f;
                sum += p;
                Ss[row4 * 72 + j] = t32(p);
            }
            sum += __shfl_xor_sync(0xffffffffu, sum, 1);
            sum += __shfl_xor_sync(0xffffffffu, sum, 2);
            l = l * corr + sum;
            m = mnew;
            if (sub == 0) crow[row4] = corr;
        }
        __syncthreads();

        // Rescale O rows by correction factor
        #pragma unroll
        for (int i = 0; i < 16; i++) {
            int idx = tid + i * 256;
            int r = idx >> 6, c = idx & 63;
            Oa[r * 68 + c] *= crow[r];
        }
        __syncthreads();

        // O += P * V  (accumulate directly into Oa via fragment round-trip)
        #pragma unroll
        for (int tt = 0; tt < 2; tt++) {
            int tile = wid * 2 + tt;
            int tm = tile >> 2, tn = tile & 3;
            wmma::fragment<wmma::accumulator, 16, 16, 8, float> oacc;
            wmma::load_matrix_sync(oacc, &Oa[tm * 16 * 68 + tn * 16], 68, wmma::mem_row_major);
            #pragma unroll
            for (int kk = 0; kk < 64; kk += 8) {
                wmma::fragment<wmma::matrix_a, 16, 16, 8, wmma::precision::tf32, wmma::row_major> pa;
                wmma::fragment<wmma::matrix_b, 16, 16, 8, wmma::precision::tf32, wmma::row_major> vb;
                wmma::load_matrix_sync(pa, &Ss[tm * 16 * 72 + kk], 72);
                wmma::load_matrix_sync(vb, &Vs[kk * 68 + tn * 16], 68);
                wmma::mma_sync(oacc, pa, vb, oacc);
            }
            wmma::store_matrix_sync(&Oa[tm * 16 * 68 + tn * 16], oacc, 68, wmma::mem_row_major);
        }
    }

    if (sub == 0) lrow[row4] = l;
    __syncthreads();

    #pragma unroll
    for (int i = 0; i < 16; i++) {
        int idx = tid + i * 256;
        int r = idx >> 6, c = idx & 63;
        Og[((long)(b * SEQ + q0 + r)) * DMODEL + h * DHEAD + c] = Oa[r * 68 + c] / lrow[r];
    }
}

// ---------------------------------------------------------------------------
// Launch
// ---------------------------------------------------------------------------
extern "C" void kernel_launch(void* const* d_in, const int* in_sizes, int n_in,
                              void* d_out, int out_size)
{
    const float* x  = (const float*)d_in[0];
    const float* wq = (const float*)d_in[1];
    const float* wk = (const float*)d_in[2];
    const float* wv = (const float*)d_in[3];
    const float* wo = (const float*)d_in[4];
    float* out = (float*)d_out;

    float *qb, *kb, *vb, *ab;
    cudaGetSymbolAddress((void**)&qb, g_q);
    cudaGetSymbolAddress((void**)&kb, g_k);
    cudaGetSymbolAddress((void**)&vb, g_v);
    cudaGetSymbolAddress((void**)&ab, g_att);

    dim3 gg(DMODEL / 128, MROWS / 128);   // (8, 64)

    gemm_tf32<<<gg, 256>>>(x, wq, qb, MROWS, DMODEL, DMODEL);
    gemm_tf32<<<gg, 256>>>(x, wk, kb, MROWS, DMODEL, DMODEL);
    gemm_tf32<<<gg, 256>>>(x, wv, vb, MROWS, DMODEL, DMODEL);

    const int fl_smem = (4 * 64 * 68 + 64 * 72 + 128) * (int)sizeof(float);  // 88576 B
    cudaFuncSetAttribute(flash_tf32, cudaFuncAttributeMaxDynamicSharedMemorySize, fl_smem);
    dim3 fg(SEQ / 64, NHEAD, BATCH);      // (32, 16, 4)
    flash_tf32<<<fg, 256, fl_smem>>>(qb, kb, vb, ab);

    gemm_tf32<<<gg, 256>>>(ab, wo, out, MROWS, DMODEL, DMODEL);
}

// round 3
// speedup vs baseline: 1.8698x; 1.6035x over previous
#include <cuda_runtime.h>
#include <mma.h>
#include <cstddef>
#include <cstdint>

using namespace nvcuda;

// Problem constants
static constexpr int BATCH  = 4;
static constexpr int SEQ    = 2048;
static constexpr int DMODEL = 1024;
static constexpr int NHEAD  = 16;
static constexpr int DHEAD  = 64;
static constexpr int MROWS  = BATCH * SEQ;   // 8192

// Scratch (device globals — no allocations allowed)
__device__ float g_q[MROWS * DMODEL];
__device__ float g_k[MROWS * DMODEL];
__device__ float g_v[MROWS * DMODEL];
__device__ float g_att[MROWS * DMODEL];

__device__ __forceinline__ float t32(float x) { return wmma::__float_to_tf32(x); }

// mma.m16n8k8 tf32, row.col, fp32 accumulate. Documented PTX fragment layouts.
__device__ __forceinline__ void mma8(float& c0, float& c1, float& c2, float& c3,
                                     uint32_t a0, uint32_t a1, uint32_t a2, uint32_t a3,
                                     uint32_t b0, uint32_t b1)
{
    asm volatile(
        "mma.sync.aligned.m16n8k8.row.col.f32.tf32.tf32.f32 "
        "{%0,%1,%2,%3}, {%4,%5,%6,%7}, {%8,%9}, {%0,%1,%2,%3};\n"
        : "+f"(c0), "+f"(c1), "+f"(c2), "+f"(c3)
        : "r"(a0), "r"(a1), "r"(a2), "r"(a3), "r"(b0), "r"(b1));
}

// ---------------------------------------------------------------------------
// TF32 GEMM: C[M,N] = A[M,K] * B[K,N], row-major fp32 in/out. (unchanged R2)
// ---------------------------------------------------------------------------
__global__ __launch_bounds__(256) void gemm_tf32(
    const float* __restrict__ A, const float* __restrict__ B,
    float* __restrict__ C, int M, int N, int K)
{
    __shared__ float As[128][36];
    __shared__ float Bs[32][136];

    const int tid = threadIdx.x;
    const int wid = tid >> 5;
    const int wm = (wid & 1) * 64;
    const int wn = (wid >> 1) * 32;
    const long bm0 = (long)blockIdx.y * 128;
    const long bn0 = (long)blockIdx.x * 128;

    wmma::fragment<wmma::accumulator, 16, 16, 8, float> acc[4][2];
    #pragma unroll
    for (int i = 0; i < 4; i++)
        #pragma unroll
        for (int j = 0; j < 2; j++)
            wmma::fill_fragment(acc[i][j], 0.0f);

    for (int k0 = 0; k0 < K; k0 += 32) {
        __syncthreads();
        #pragma unroll
        for (int r = 0; r < 4; r++) {
            int idx = tid + r * 256;
            int row = idx >> 3, c = (idx & 7) << 2;
            float4 v = *(const float4*)(A + (bm0 + row) * (long)K + k0 + c);
            As[row][c + 0] = t32(v.x);
            As[row][c + 1] = t32(v.y);
            As[row][c + 2] = t32(v.z);
            As[row][c + 3] = t32(v.w);
        }
        #pragma unroll
        for (int r = 0; r < 4; r++) {
            int idx = tid + r * 256;
            int row = idx >> 5, c = (idx & 31) << 2;
            float4 v = *(const float4*)(B + (long)(k0 + row) * N + bn0 + c);
            Bs[row][c + 0] = t32(v.x);
            Bs[row][c + 1] = t32(v.y);
            Bs[row][c + 2] = t32(v.z);
            Bs[row][c + 3] = t32(v.w);
        }
        __syncthreads();

        #pragma unroll
        for (int kk = 0; kk < 32; kk += 8) {
            wmma::fragment<wmma::matrix_a, 16, 16, 8, wmma::precision::tf32, wmma::row_major> af[4];
            wmma::fragment<wmma::matrix_b, 16, 16, 8, wmma::precision::tf32, wmma::row_major> bf[2];
            #pragma unroll
            for (int i = 0; i < 4; i++)
                wmma::load_matrix_sync(af[i], &As[wm + i * 16][kk], 36);
            #pragma unroll
            for (int j = 0; j < 2; j++)
                wmma::load_matrix_sync(bf[j], &Bs[kk][wn + j * 16], 136);
            #pragma unroll
            for (int i = 0; i < 4; i++)
                #pragma unroll
                for (int j = 0; j < 2; j++)
                    wmma::mma_sync(acc[i][j], af[i], bf[j], acc[i][j]);
        }
    }

    #pragma unroll
    for (int i = 0; i < 4; i++)
        #pragma unroll
        for (int j = 0; j < 2; j++)
            wmma::store_matrix_sync(C + (bm0 + wm + i * 16) * (long)N + bn0 + wn + j * 16,
                                    acc[i][j], N, wmma::mem_row_major);
}

// ---------------------------------------------------------------------------
// Flash attention v3 (causal), FA2-style register-resident tf32 mma.
// CTA = 64 queries, 128 threads = 4 warps, 16 query rows per warp.
// Q fragments + O accumulators in registers the whole kernel; S in registers;
// softmax in registers (quad shfl); only P transits per-warp smem scratch.
// Smem strides: Ks 76 / Vs 72 (conflict-free B-frag reads), Ps 72.
// ---------------------------------------------------------------------------
static constexpr int KS_STRIDE = 76;
static constexpr int VS_STRIDE = 72;
static constexpr int PS_STRIDE = 72;

__global__ __launch_bounds__(128) void flash3(
    const float* __restrict__ Qg, const float* __restrict__ Kg,
    const float* __restrict__ Vg, float* __restrict__ Og)
{
    extern __shared__ float sm[];
    float* Ks = sm;                               // [64][76]
    float* Vs = Ks + 64 * KS_STRIDE;              // [64][72]
    float* Psb = Vs + 64 * VS_STRIDE;             // 4 x [16][72]

    const int tid = threadIdx.x;
    const int w   = tid >> 5;
    const int l   = tid & 31;
    const int g   = l >> 2;        // group id 0..7
    const int qd  = l & 3;         // thread-in-group 0..3
    const int b = blockIdx.z, h = blockIdx.y;
    const int q0 = blockIdx.x * 64;
    float* Ps = Psb + w * 16 * PS_STRIDE;

    // ---- Stage Q tile into Ks (scaled by 1/8, tf32), pull fragments to regs
    #pragma unroll
    for (int r = 0; r < 8; r++) {
        int idx = tid + r * 128;
        int row = idx >> 4, c = (idx & 15) << 2;
        float4 v = *(const float4*)(Qg + ((long)(b * SEQ + q0 + row)) * DMODEL + h * DHEAD + c);
        Ks[row * KS_STRIDE + c + 0] = t32(v.x * 0.125f);
        Ks[row * KS_STRIDE + c + 1] = t32(v.y * 0.125f);
        Ks[row * KS_STRIDE + c + 2] = t32(v.z * 0.125f);
        Ks[row * KS_STRIDE + c + 3] = t32(v.w * 0.125f);
    }
    __syncthreads();

    uint32_t qa[8][4];
    {
        const int r0 = (w * 16 + g) * KS_STRIDE;
        const int r1 = (w * 16 + g + 8) * KS_STRIDE;
        #pragma unroll
        for (int k = 0; k < 8; k++) {
            qa[k][0] = __float_as_uint(Ks[r0 + k * 8 + qd]);
            qa[k][1] = __float_as_uint(Ks[r1 + k * 8 + qd]);
            qa[k][2] = __float_as_uint(Ks[r0 + k * 8 + qd + 4]);
            qa[k][3] = __float_as_uint(Ks[r1 + k * 8 + qd + 4]);
        }
    }

    float oacc[8][4];
    #pragma unroll
    for (int n = 0; n < 8; n++)
        #pragma unroll
        for (int e = 0; e < 4; e++) oacc[n][e] = 0.0f;
    float m0 = -1e30f, m1 = -1e30f, l0 = 0.0f, l1 = 0.0f;

    const int ntiles = blockIdx.x + 1;
    for (int t = 0; t < ntiles; t++) {
        const int k0 = t * 64;
        __syncthreads();   // prior tile's Ks/Vs consumers done (incl. Q frag reads)

        // ---- Load K/V tile (tf32)
        #pragma unroll
        for (int r = 0; r < 8; r++) {
            int idx = tid + r * 128;
            int row = idx >> 4, c = (idx & 15) << 2;
            long base = ((long)(b * SEQ + k0 + row)) * DMODEL + h * DHEAD + c;
            float4 kv = *(const float4*)(Kg + base);
            Ks[row * KS_STRIDE + c + 0] = t32(kv.x);
            Ks[row * KS_STRIDE + c + 1] = t32(kv.y);
            Ks[row * KS_STRIDE + c + 2] = t32(kv.z);
            Ks[row * KS_STRIDE + c + 3] = t32(kv.w);
            float4 vv = *(const float4*)(Vg + base);
            Vs[row * VS_STRIDE + c + 0] = t32(vv.x);
            Vs[row * VS_STRIDE + c + 1] = t32(vv.y);
            Vs[row * VS_STRIDE + c + 2] = t32(vv.z);
            Vs[row * VS_STRIDE + c + 3] = t32(vv.w);
        }
        __syncthreads();

        // ---- S = Q * K^T  (register accumulators, 8 n-tiles of 16x8)
        float sacc[8][4];
        #pragma unroll
        for (int n = 0; n < 8; n++) {
            sacc[n][0] = sacc[n][1] = sacc[n][2] = sacc[n][3] = 0.0f;
            const int krow = (n * 8 + g) * KS_STRIDE;
            #pragma unroll
            for (int k = 0; k < 8; k++) {
                uint32_t b0 = __float_as_uint(Ks[krow + k * 8 + qd]);
                uint32_t b1 = __float_as_uint(Ks[krow + k * 8 + qd + 4]);
                mma8(sacc[n][0], sacc[n][1], sacc[n][2], sacc[n][3],
                     qa[k][0], qa[k][1], qa[k][2], qa[k][3], b0, b1);
            }
        }

        // ---- Causal mask (only the diagonal tile needs it)
        if (t == ntiles - 1) {
            const int r0 = w * 16 + g, r1 = r0 + 8;
            #pragma unroll
            for (int n = 0; n < 8; n++) {
                int c0 = n * 8 + 2 * qd, c1 = c0 + 1;
                if (c0 > r0) sacc[n][0] = -1e30f;
                if (c1 > r0) sacc[n][1] = -1e30f;
                if (c0 > r1) sacc[n][2] = -1e30f;
                if (c1 > r1) sacc[n][3] = -1e30f;
            }
        }

        // ---- Online softmax in registers (rows g and g+8; quad reduction)
        float mx0 = -1e30f, mx1 = -1e30f;
        #pragma unroll
        for (int n = 0; n < 8; n++) {
            mx0 = fmaxf(mx0, fmaxf(sacc[n][0], sacc[n][1]));
            mx1 = fmaxf(mx1, fmaxf(sacc[n][2], sacc[n][3]));
        }
        mx0 = fmaxf(mx0, __shfl_xor_sync(0xffffffffu, mx0, 1));
        mx0 = fmaxf(mx0, __shfl_xor_sync(0xffffffffu, mx0, 2));
        mx1 = fmaxf(mx1, __shfl_xor_sync(0xffffffffu, mx1, 1));
        mx1 = fmaxf(mx1, __shfl_xor_sync(0xffffffffu, mx1, 2));
        const float mn0 = fmaxf(m0, mx0);
        const float mn1 = fmaxf(m1, mx1);
        const float cr0 = __expf(m0 - mn0);
        const float cr1 = __expf(m1 - mn1);

        float s0 = 0.0f, s1 = 0.0f;
        #pragma unroll
        for (int n = 0; n < 8; n++) {
            float p0 = __expf(sacc[n][0] - mn0);
            float p1 = __expf(sacc[n][1] - mn0);
            float p2 = __expf(sacc[n][2] - mn1);
            float p3 = __expf(sacc[n][3] - mn1);
            s0 += p0 + p1;
            s1 += p2 + p3;
            // park P (tf32) in per-warp smem scratch, C-layout
            *(float2*)&Ps[g * PS_STRIDE + n * 8 + 2 * qd]       = make_float2(t32(p0), t32(p1));
            *(float2*)&Ps[(g + 8) * PS_STRIDE + n * 8 + 2 * qd] = make_float2(t32(p2), t32(p3));
        }
        s0 += __shfl_xor_sync(0xffffffffu, s0, 1);
        s0 += __shfl_xor_sync(0xffffffffu, s0, 2);
        s1 += __shfl_xor_sync(0xffffffffu, s1, 1);
        s1 += __shfl_xor_sync(0xffffffffu, s1, 2);
        l0 = l0 * cr0 + s0;
        l1 = l1 * cr1 + s1;
        m0 = mn0;
        m1 = mn1;

        // rescale O accumulators (registers, no smem)
        #pragma unroll
        for (int n = 0; n < 8; n++) {
            oacc[n][0] *= cr0; oacc[n][1] *= cr0;
            oacc[n][2] *= cr1; oacc[n][3] *= cr1;
        }
        __syncwarp();

        // ---- O += P * V
        #pragma unroll
        for (int k = 0; k < 8; k++) {
            uint32_t pa0 = __float_as_uint(Ps[g * PS_STRIDE + k * 8 + qd]);
            uint32_t pa1 = __float_as_uint(Ps[(g + 8) * PS_STRIDE + k * 8 + qd]);
            uint32_t pa2 = __float_as_uint(Ps[g * PS_STRIDE + k * 8 + qd + 4]);
            uint32_t pa3 = __float_as_uint(Ps[(g + 8) * PS_STRIDE + k * 8 + qd + 4]);
            #pragma unroll
            for (int n = 0; n < 8; n++) {
                uint32_t b0 = __float_as_uint(Vs[(k * 8 + qd) * VS_STRIDE + n * 8 + g]);
                uint32_t b1 = __float_as_uint(Vs[(k * 8 + qd + 4) * VS_STRIDE + n * 8 + g]);
                mma8(oacc[n][0], oacc[n][1], oacc[n][2], oacc[n][3],
                     pa0, pa1, pa2, pa3, b0, b1);
            }
        }
    }

    // ---- Epilogue: normalize and write (float2 per n-tile per row)
    const float inv0 = 1.0f / l0;
    const float inv1 = 1.0f / l1;
    const long row0 = (long)(b * SEQ + q0 + w * 16 + g);
    const long row1 = row0 + 8;
    #pragma unroll
    for (int n = 0; n < 8; n++) {
        int c = h * DHEAD + n * 8 + 2 * qd;
        *(float2*)(Og + row0 * DMODEL + c) = make_float2(oacc[n][0] * inv0, oacc[n][1] * inv0);
        *(float2*)(Og + row1 * DMODEL + c) = make_float2(oacc[n][2] * inv1, oacc[n][3] * inv1);
    }
}

// ---------------------------------------------------------------------------
// Launch
// ---------------------------------------------------------------------------
extern "C" void kernel_launch(void* const* d_in, const int* in_sizes, int n_in,
                              void* d_out, int out_size)
{
    const float* x  = (const float*)d_in[0];
    const float* wq = (const float*)d_in[1];
    const float* wk = (const float*)d_in[2];
    const float* wv = (const float*)d_in[3];
    const float* wo = (const float*)d_in[4];
    float* out = (float*)d_out;

    float *qb, *kb, *vb, *ab;
    cudaGetSymbolAddress((void**)&qb, g_q);
    cudaGetSymbolAddress((void**)&kb, g_k);
    cudaGetSymbolAddress((void**)&vb, g_v);
    cudaGetSymbolAddress((void**)&ab, g_att);

    dim3 gg(DMODEL / 128, MROWS / 128);   // (8, 64)

    gemm_tf32<<<gg, 256>>>(x, wq, qb, MROWS, DMODEL, DMODEL);
    gemm_tf32<<<gg, 256>>>(x, wk, kb, MROWS, DMODEL, DMODEL);
    gemm_tf32<<<gg, 256>>>(x, wv, vb, MROWS, DMODEL, DMODEL);

    const int fl_smem = (64 * KS_STRIDE + 64 * VS_STRIDE + 4 * 16 * PS_STRIDE) * (int)sizeof(float);
    cudaFuncSetAttribute(flash3, cudaFuncAttributeMaxDynamicSharedMemorySize, fl_smem);
    dim3 fg(SEQ / 64, NHEAD, BATCH);      // (32, 16, 4)
    flash3<<<fg, 128, fl_smem>>>(qb, kb, vb, ab);

    gemm_tf32<<<gg, 256>>>(ab, wo, out, MROWS, DMODEL, DMODEL);
}

// round 4
// speedup vs baseline: 2.0564x; 1.0998x over previous
#include <cuda_runtime.h>
#include <mma.h>
#include <cstddef>
#include <cstdint>

using namespace nvcuda;

// Problem constants
static constexpr int BATCH  = 4;
static constexpr int SEQ    = 2048;
static constexpr int DMODEL = 1024;
static constexpr int NHEAD  = 16;
static constexpr int DHEAD  = 64;
static constexpr int MROWS  = BATCH * SEQ;   // 8192

// Scratch (device globals — no allocations allowed)
__device__ float g_q[MROWS * DMODEL];
__device__ float g_k[MROWS * DMODEL];
__device__ float g_v[MROWS * DMODEL];
__device__ float g_att[MROWS * DMODEL];

__device__ __forceinline__ float t32(float x) { return wmma::__float_to_tf32(x); }

// mma.m16n8k8 tf32, row.col, fp32 accumulate.
__device__ __forceinline__ void mma8(float& c0, float& c1, float& c2, float& c3,
                                     uint32_t a0, uint32_t a1, uint32_t a2, uint32_t a3,
                                     uint32_t b0, uint32_t b1)
{
    asm volatile(
        "mma.sync.aligned.m16n8k8.row.col.f32.tf32.tf32.f32 "
        "{%0,%1,%2,%3}, {%4,%5,%6,%7}, {%8,%9}, {%0,%1,%2,%3};\n"
        : "+f"(c0), "+f"(c1), "+f"(c2), "+f"(c3)
        : "r"(a0), "r"(a1), "r"(a2), "r"(a3), "r"(b0), "r"(b1));
}

// ---------------------------------------------------------------------------
// TF32 GEMM, register-prefetch software pipeline.
// C[M,N] = A[M,K] * B[K,N], row-major fp32 in/out.
// 128x128x32 tile, 256 threads = 8 warps, warp tile 64x32, wmma m16n16k8.
// Next k-chunk is loaded to registers DURING compute on the current smem
// tiles; tf32 RN rounding happens at smem-fill. Optional QKV fusion via
// blockIdx.z-selected operand sets.
// ---------------------------------------------------------------------------
template <int NMAT>
__global__ __launch_bounds__(256) void gemm_tf32_pipe(
    const float* __restrict__ A,
    const float* __restrict__ B0, const float* __restrict__ B1, const float* __restrict__ B2,
    float* __restrict__ C0, float* __restrict__ C1, float* __restrict__ C2,
    int M, int N, int K)
{
    __shared__ float As[128][36];
    __shared__ float Bs[32][136];

    const float* B = B0;
    float* C = C0;
    if (NMAT > 1) {
        if (blockIdx.z == 1) { B = B1; C = C1; }
        else if (blockIdx.z == 2) { B = B2; C = C2; }
    }

    const int tid = threadIdx.x;
    const int wid = tid >> 5;
    const int wm = (wid & 1) * 64;
    const int wn = (wid >> 1) * 32;
    const long bm0 = (long)blockIdx.y * 128;
    const long bn0 = (long)blockIdx.x * 128;

    // global load assignments (same pattern each chunk)
    const int arow = tid >> 3;             // 0..127  (wait: 256 threads -> need 4 iters)
    const int acol = (tid & 7) << 2;       // 0..28
    const int brow = tid >> 5;             // 0..7 base
    const int bcol = (tid & 31) << 2;      // 0..124

    wmma::fragment<wmma::accumulator, 16, 16, 8, float> acc[4][2];
    #pragma unroll
    for (int i = 0; i < 4; i++)
        #pragma unroll
        for (int j = 0; j < 2; j++)
            wmma::fill_fragment(acc[i][j], 0.0f);

    float4 a_reg[4], b_reg[4];

    // ---- prologue: load k-chunk 0 into registers, park in smem
    #pragma unroll
    for (int r = 0; r < 4; r++) {
        int idx = tid + r * 256;
        a_reg[r] = *(const float4*)(A + (bm0 + (idx >> 3)) * (long)K + ((idx & 7) << 2));
        b_reg[r] = *(const float4*)(B + (long)((idx >> 5)) * N + bn0 + ((idx & 31) << 2));
    }
    #pragma unroll
    for (int r = 0; r < 4; r++) {
        int idx = tid + r * 256;
        int ar = idx >> 3, ac = (idx & 7) << 2;
        As[ar][ac + 0] = t32(a_reg[r].x);
        As[ar][ac + 1] = t32(a_reg[r].y);
        As[ar][ac + 2] = t32(a_reg[r].z);
        As[ar][ac + 3] = t32(a_reg[r].w);
        int br = idx >> 5, bc = (idx & 31) << 2;
        Bs[br][bc + 0] = t32(b_reg[r].x);
        Bs[br][bc + 1] = t32(b_reg[r].y);
        Bs[br][bc + 2] = t32(b_reg[r].z);
        Bs[br][bc + 3] = t32(b_reg[r].w);
    }
    __syncthreads();

    for (int k0 = 32; k0 <= K; k0 += 32) {
        const bool more = (k0 < K);
        // ---- prefetch next chunk into registers (in flight during compute)
        if (more) {
            #pragma unroll
            for (int r = 0; r < 4; r++) {
                int idx = tid + r * 256;
                a_reg[r] = *(const float4*)(A + (bm0 + (idx >> 3)) * (long)K + k0 + ((idx & 7) << 2));
                b_reg[r] = *(const float4*)(B + (long)(k0 + (idx >> 5)) * N + bn0 + ((idx & 31) << 2));
            }
        }

        // ---- compute current chunk from smem
        #pragma unroll
        for (int kk = 0; kk < 32; kk += 8) {
            wmma::fragment<wmma::matrix_a, 16, 16, 8, wmma::precision::tf32, wmma::row_major> af[4];
            wmma::fragment<wmma::matrix_b, 16, 16, 8, wmma::precision::tf32, wmma::row_major> bf[2];
            #pragma unroll
            for (int i = 0; i < 4; i++)
                wmma::load_matrix_sync(af[i], &As[wm + i * 16][kk], 36);
            #pragma unroll
            for (int j = 0; j < 2; j++)
                wmma::load_matrix_sync(bf[j], &Bs[kk][wn + j * 16], 136);
            #pragma unroll
            for (int i = 0; i < 4; i++)
                #pragma unroll
                for (int j = 0; j < 2; j++)
                    wmma::mma_sync(acc[i][j], af[i], bf[j], acc[i][j]);
        }

        // ---- publish prefetched chunk
        if (more) {
            __syncthreads();
            #pragma unroll
            for (int r = 0; r < 4; r++) {
                int idx = tid + r * 256;
                int ar = idx >> 3, ac = (idx & 7) << 2;
                As[ar][ac + 0] = t32(a_reg[r].x);
                As[ar][ac + 1] = t32(a_reg[r].y);
                As[ar][ac + 2] = t32(a_reg[r].z);
                As[ar][ac + 3] = t32(a_reg[r].w);
                int br = idx >> 5, bc = (idx & 31) << 2;
                Bs[br][bc + 0] = t32(b_reg[r].x);
                Bs[br][bc + 1] = t32(b_reg[r].y);
                Bs[br][bc + 2] = t32(b_reg[r].z);
                Bs[br][bc + 3] = t32(b_reg[r].w);
            }
            __syncthreads();
        }
    }

    #pragma unroll
    for (int i = 0; i < 4; i++)
        #pragma unroll
        for (int j = 0; j < 2; j++)
            wmma::store_matrix_sync(C + (bm0 + wm + i * 16) * (long)N + bn0 + wn + j * 16,
                                    acc[i][j], N, wmma::mem_row_major);
}

// ---------------------------------------------------------------------------
// Flash attention (unchanged from R3): FA2-style register-resident tf32 mma.
// ---------------------------------------------------------------------------
static constexpr int KS_STRIDE = 76;
static constexpr int VS_STRIDE = 72;
static constexpr int PS_STRIDE = 72;

__global__ __launch_bounds__(128) void flash3(
    const float* __restrict__ Qg, const float* __restrict__ Kg,
    const float* __restrict__ Vg, float* __restrict__ Og)
{
    extern __shared__ float sm[];
    float* Ks = sm;                               // [64][76]
    float* Vs = Ks + 64 * KS_STRIDE;              // [64][72]
    float* Psb = Vs + 64 * VS_STRIDE;             // 4 x [16][72]

    const int tid = threadIdx.x;
    const int w   = tid >> 5;
    const int l   = tid & 31;
    const int g   = l >> 2;
    const int qd  = l & 3;
    const int b = blockIdx.z, h = blockIdx.y;
    const int q0 = blockIdx.x * 64;
    float* Ps = Psb + w * 16 * PS_STRIDE;

    #pragma unroll
    for (int r = 0; r < 8; r++) {
        int idx = tid + r * 128;
        int row = idx >> 4, c = (idx & 15) << 2;
        float4 v = *(const float4*)(Qg + ((long)(b * SEQ + q0 + row)) * DMODEL + h * DHEAD + c);
        Ks[row * KS_STRIDE + c + 0] = t32(v.x * 0.125f);
        Ks[row * KS_STRIDE + c + 1] = t32(v.y * 0.125f);
        Ks[row * KS_STRIDE + c + 2] = t32(v.z * 0.125f);
        Ks[row * KS_STRIDE + c + 3] = t32(v.w * 0.125f);
    }
    __syncthreads();

    uint32_t qa[8][4];
    {
        const int r0 = (w * 16 + g) * KS_STRIDE;
        const int r1 = (w * 16 + g + 8) * KS_STRIDE;
        #pragma unroll
        for (int k = 0; k < 8; k++) {
            qa[k][0] = __float_as_uint(Ks[r0 + k * 8 + qd]);
            qa[k][1] = __float_as_uint(Ks[r1 + k * 8 + qd]);
            qa[k][2] = __float_as_uint(Ks[r0 + k * 8 + qd + 4]);
            qa[k][3] = __float_as_uint(Ks[r1 + k * 8 + qd + 4]);
        }
    }

    float oacc[8][4];
    #pragma unroll
    for (int n = 0; n < 8; n++)
        #pragma unroll
        for (int e = 0; e < 4; e++) oacc[n][e] = 0.0f;
    float m0 = -1e30f, m1 = -1e30f, l0 = 0.0f, l1 = 0.0f;

    const int ntiles = blockIdx.x + 1;
    for (int t = 0; t < ntiles; t++) {
        const int k0 = t * 64;
        __syncthreads();

        #pragma unroll
        for (int r = 0; r < 8; r++) {
            int idx = tid + r * 128;
            int row = idx >> 4, c = (idx & 15) << 2;
            long base = ((long)(b * SEQ + k0 + row)) * DMODEL + h * DHEAD + c;
            float4 kv = *(const float4*)(Kg + base);
            Ks[row * KS_STRIDE + c + 0] = t32(kv.x);
            Ks[row * KS_STRIDE + c + 1] = t32(kv.y);
            Ks[row * KS_STRIDE + c + 2] = t32(kv.z);
            Ks[row * KS_STRIDE + c + 3] = t32(kv.w);
            float4 vv = *(const float4*)(Vg + base);
            Vs[row * VS_STRIDE + c + 0] = t32(vv.x);
            Vs[row * VS_STRIDE + c + 1] = t32(vv.y);
            Vs[row * VS_STRIDE + c + 2] = t32(vv.z);
            Vs[row * VS_STRIDE + c + 3] = t32(vv.w);
        }
        __syncthreads();

        float sacc[8][4];
        #pragma unroll
        for (int n = 0; n < 8; n++) {
            sacc[n][0] = sacc[n][1] = sacc[n][2] = sacc[n][3] = 0.0f;
            const int krow = (n * 8 + g) * KS_STRIDE;
            #pragma unroll
            for (int k = 0; k < 8; k++) {
                uint32_t b0 = __float_as_uint(Ks[krow + k * 8 + qd]);
                uint32_t b1 = __float_as_uint(Ks[krow + k * 8 + qd + 4]);
                mma8(sacc[n][0], sacc[n][1], sacc[n][2], sacc[n][3],
                     qa[k][0], qa[k][1], qa[k][2], qa[k][3], b0, b1);
            }
        }

        if (t == ntiles - 1) {
            const int r0 = w * 16 + g, r1 = r0 + 8;
            #pragma unroll
            for (int n = 0; n < 8; n++) {
                int c0 = n * 8 + 2 * qd, c1 = c0 + 1;
                if (c0 > r0) sacc[n][0] = -1e30f;
                if (c1 > r0) sacc[n][1] = -1e30f;
                if (c0 > r1) sacc[n][2] = -1e30f;
                if (c1 > r1) sacc[n][3] = -1e30f;
            }
        }

        float mx0 = -1e30f, mx1 = -1e30f;
        #pragma unroll
        for (int n = 0; n < 8; n++) {
            mx0 = fmaxf(mx0, fmaxf(sacc[n][0], sacc[n][1]));
            mx1 = fmaxf(mx1, fmaxf(sacc[n][2], sacc[n][3]));
        }
        mx0 = fmaxf(mx0, __shfl_xor_sync(0xffffffffu, mx0, 1));
        mx0 = fmaxf(mx0, __shfl_xor_sync(0xffffffffu, mx0, 2));
        mx1 = fmaxf(mx1, __shfl_xor_sync(0xffffffffu, mx1, 1));
        mx1 = fmaxf(mx1, __shfl_xor_sync(0xffffffffu, mx1, 2));
        const float mn0 = fmaxf(m0, mx0);
        const float mn1 = fmaxf(m1, mx1);
        const float cr0 = __expf(m0 - mn0);
        const float cr1 = __expf(m1 - mn1);

        float s0 = 0.0f, s1 = 0.0f;
        #pragma unroll
        for (int n = 0; n < 8; n++) {
            float p0 = __expf(sacc[n][0] - mn0);
            float p1 = __expf(sacc[n][1] - mn0);
            float p2 = __expf(sacc[n][2] - mn1);
            float p3 = __expf(sacc[n][3] - mn1);
            s0 += p0 + p1;
            s1 += p2 + p3;
            *(float2*)&Ps[g * PS_STRIDE + n * 8 + 2 * qd]       = make_float2(t32(p0), t32(p1));
            *(float2*)&Ps[(g + 8) * PS_STRIDE + n * 8 + 2 * qd] = make_float2(t32(p2), t32(p3));
        }
        s0 += __shfl_xor_sync(0xffffffffu, s0, 1);
        s0 += __shfl_xor_sync(0xffffffffu, s0, 2);
        s1 += __shfl_xor_sync(0xffffffffu, s1, 1);
        s1 += __shfl_xor_sync(0xffffffffu, s1, 2);
        l0 = l0 * cr0 + s0;
        l1 = l1 * cr1 + s1;
        m0 = mn0;
        m1 = mn1;

        #pragma unroll
        for (int n = 0; n < 8; n++) {
            oacc[n][0] *= cr0; oacc[n][1] *= cr0;
            oacc[n][2] *= cr1; oacc[n][3] *= cr1;
        }
        __syncwarp();

        #pragma unroll
        for (int k = 0; k < 8; k++) {
            uint32_t pa0 = __float_as_uint(Ps[g * PS_STRIDE + k * 8 + qd]);
            uint32_t pa1 = __float_as_uint(Ps[(g + 8) * PS_STRIDE + k * 8 + qd]);
            uint32_t pa2 = __float_as_uint(Ps[g * PS_STRIDE + k * 8 + qd + 4]);
            uint32_t pa3 = __float_as_uint(Ps[(g + 8) * PS_STRIDE + k * 8 + qd + 4]);
            #pragma unroll
            for (int n = 0; n < 8; n++) {
                uint32_t b0 = __float_as_uint(Vs[(k * 8 + qd) * VS_STRIDE + n * 8 + g]);
                uint32_t b1 = __float_as_uint(Vs[(k * 8 + qd + 4) * VS_STRIDE + n * 8 + g]);
                mma8(oacc[n][0], oacc[n][1], oacc[n][2], oacc[n][3],
                     pa0, pa1, pa2, pa3, b0, b1);
            }
        }
    }

    const float inv0 = 1.0f / l0;
    const float inv1 = 1.0f / l1;
    const long row0 = (long)(b * SEQ + q0 + w * 16 + g);
    const long row1 = row0 + 8;
    #pragma unroll
    for (int n = 0; n < 8; n++) {
        int c = h * DHEAD + n * 8 + 2 * qd;
        *(float2*)(Og + row0 * DMODEL + c) = make_float2(oacc[n][0] * inv0, oacc[n][1] * inv0);
        *(float2*)(Og + row1 * DMODEL + c) = make_float2(oacc[n][2] * inv1, oacc[n][3] * inv1);
    }
}

// ---------------------------------------------------------------------------
// Launch
// ---------------------------------------------------------------------------
extern "C" void kernel_launch(void* const* d_in, const int* in_sizes, int n_in,
                              void* d_out, int out_size)
{
    const float* x  = (const float*)d_in[0];
    const float* wq = (const float*)d_in[1];
    const float* wk = (const float*)d_in[2];
    const float* wv = (const float*)d_in[3];
    const float* wo = (const float*)d_in[4];
    float* out = (float*)d_out;

    float *qb, *kb, *vb, *ab;
    cudaGetSymbolAddress((void**)&qb, g_q);
    cudaGetSymbolAddress((void**)&kb, g_k);
    cudaGetSymbolAddress((void**)&vb, g_v);
    cudaGetSymbolAddress((void**)&ab, g_att);

    // Fused QKV projection: one launch, blockIdx.z selects {W,C}.
    dim3 gq(DMODEL / 128, MROWS / 128, 3);   // (8, 64, 3)
    gemm_tf32_pipe<3><<<gq, 256>>>(x, wq, wk, wv, qb, kb, vb, MROWS, DMODEL, DMODEL);

    const int fl_smem = (64 * KS_STRIDE + 64 * VS_STRIDE + 4 * 16 * PS_STRIDE) * (int)sizeof(float);
    cudaFuncSetAttribute(flash3, cudaFuncAttributeMaxDynamicSharedMemorySize, fl_smem);
    dim3 fg(SEQ / 64, NHEAD, BATCH);         // (32, 16, 4)
    flash3<<<fg, 128, fl_smem>>>(qb, kb, vb, ab);

    dim3 go(DMODEL / 128, MROWS / 128, 1);   // (8, 64)
    gemm_tf32_pipe<1><<<go, 256>>>(ab, wo, nullptr, nullptr, out, nullptr, nullptr,
                                   MROWS, DMODEL, DMODEL);
}

// round 5
// speedup vs baseline: 3.5659x; 1.7341x over previous
#include <cuda_runtime.h>
#include <mma.h>
#include <cstddef>
#include <cstdint>

using namespace nvcuda;

// Problem constants
static constexpr int BATCH  = 4;
static constexpr int SEQ    = 2048;
static constexpr int DMODEL = 1024;
static constexpr int NHEAD  = 16;
static constexpr int DHEAD  = 64;
static constexpr int MROWS  = BATCH * SEQ;   // 8192

// Scratch (device globals — no allocations allowed)
__device__ float g_q[MROWS * DMODEL];
__device__ float g_k[MROWS * DMODEL];
__device__ float g_v[MROWS * DMODEL];
__device__ float g_att[MROWS * DMODEL];

__device__ __forceinline__ float t32(float x) { return wmma::__float_to_tf32(x); }

// mma.m16n8k8 tf32, row.col, fp32 accumulate.
__device__ __forceinline__ void mma8(float& c0, float& c1, float& c2, float& c3,
                                     uint32_t a0, uint32_t a1, uint32_t a2, uint32_t a3,
                                     uint32_t b0, uint32_t b1)
{
    asm volatile(
        "mma.sync.aligned.m16n8k8.row.col.f32.tf32.tf32.f32 "
        "{%0,%1,%2,%3}, {%4,%5,%6,%7}, {%8,%9}, {%0,%1,%2,%3};\n"
        : "+f"(c0), "+f"(c1), "+f"(c2), "+f"(c3)
        : "r"(a0), "r"(a1), "r"(a2), "r"(a3), "r"(b0), "r"(b1));
}

// ---------------------------------------------------------------------------
// Raw-mma TF32 GEMM, double-buffered smem + register prefetch.
// C[M,N] = A[M,K] * B[K,N], row-major fp32 in/out.
// 128x128x32 block tile, 256 threads = 8 warps, warp tile 64x32 (4x4 mma
// tiles of 16x8). Smem strides: A 36 (banks 4g+qd, conflict-free),
// B 136 (banks 8qd+g, conflict-free). One __syncthreads per k-chunk.
// tf32 RN rounding at smem fill. QKV fusion via blockIdx.z.
// ---------------------------------------------------------------------------
static constexpr int AS_STRIDE = 36;
static constexpr int BS_STRIDE = 136;
static constexpr int AS_BUF = 128 * AS_STRIDE;   // 4608 floats
static constexpr int BS_BUF = 32 * BS_STRIDE;    // 4352 floats
static constexpr int GEMM_SMEM = (2 * AS_BUF + 2 * BS_BUF) * (int)sizeof(float); // 71680 B

template <int NMAT>
__global__ __launch_bounds__(256) void gemm_raw(
    const float* __restrict__ A,
    const float* __restrict__ B0, const float* __restrict__ B1, const float* __restrict__ B2,
    float* __restrict__ C0, float* __restrict__ C1, float* __restrict__ C2,
    int M, int N, int K)
{
    extern __shared__ float smem[];
    float* As = smem;                 // [2][128][36]
    float* Bs = smem + 2 * AS_BUF;    // [2][32][136]

    const float* B = B0;
    float* C = C0;
    if (NMAT > 1) {
        if (blockIdx.z == 1) { B = B1; C = C1; }
        else if (blockIdx.z == 2) { B = B2; C = C2; }
    }

    const int tid = threadIdx.x;
    const int wid = tid >> 5;
    const int l   = tid & 31;
    const int g   = l >> 2;      // 0..7
    const int qd  = l & 3;       // 0..3
    const int wm  = (wid & 1) * 64;
    const int wn  = (wid >> 1) * 32;
    const long bm0 = (long)blockIdx.y * 128;
    const long bn0 = (long)blockIdx.x * 128;

    // per-thread global load coords (4 float4 each for A and B per chunk)
    // A: 128 rows x 32 cols;  B: 32 rows x 128 cols
    float acc[4][4][4];
    #pragma unroll
    for (int i = 0; i < 4; i++)
        #pragma unroll
        for (int j = 0; j < 4; j++)
            #pragma unroll
            for (int e = 0; e < 4; e++) acc[i][j][e] = 0.0f;

    float4 a_reg[4], b_reg[4];

    // ---- prologue: chunk 0 -> regs -> smem buf 0
    #pragma unroll
    for (int r = 0; r < 4; r++) {
        int idx = tid + r * 256;
        a_reg[r] = *(const float4*)(A + (bm0 + (idx >> 3)) * (long)K + ((idx & 7) << 2));
        b_reg[r] = *(const float4*)(B + (long)(idx >> 5) * N + bn0 + ((idx & 31) << 2));
    }
    #pragma unroll
    for (int r = 0; r < 4; r++) {
        int idx = tid + r * 256;
        float* ap = &As[(idx >> 3) * AS_STRIDE + ((idx & 7) << 2)];
        ap[0] = t32(a_reg[r].x); ap[1] = t32(a_reg[r].y);
        ap[2] = t32(a_reg[r].z); ap[3] = t32(a_reg[r].w);
        float* bp = &Bs[(idx >> 5) * BS_STRIDE + ((idx & 31) << 2)];
        bp[0] = t32(b_reg[r].x); bp[1] = t32(b_reg[r].y);
        bp[2] = t32(b_reg[r].z); bp[3] = t32(b_reg[r].w);
    }
    __syncthreads();

    int cur = 0;
    for (int k0 = 32; k0 <= K; k0 += 32) {
        const bool more = (k0 < K);
        // prefetch next chunk to registers (in flight during compute)
        if (more) {
            #pragma unroll
            for (int r = 0; r < 4; r++) {
                int idx = tid + r * 256;
                a_reg[r] = *(const float4*)(A + (bm0 + (idx >> 3)) * (long)K + k0 + ((idx & 7) << 2));
                b_reg[r] = *(const float4*)(B + (long)(k0 + (idx >> 5)) * N + bn0 + ((idx & 31) << 2));
            }
        }

        // compute current chunk from smem buffer `cur`
        const float* Ac = As + cur * AS_BUF;
        const float* Bc = Bs + cur * BS_BUF;
        #pragma unroll
        for (int kk = 0; kk < 32; kk += 8) {
            uint32_t af[4][4];
            #pragma unroll
            for (int tm = 0; tm < 4; tm++) {
                const int r0 = (wm + tm * 16 + g) * AS_STRIDE + kk;
                const int r1 = r0 + 8 * AS_STRIDE;
                af[tm][0] = __float_as_uint(Ac[r0 + qd]);
                af[tm][1] = __float_as_uint(Ac[r1 + qd]);
                af[tm][2] = __float_as_uint(Ac[r0 + qd + 4]);
                af[tm][3] = __float_as_uint(Ac[r1 + qd + 4]);
            }
            uint32_t bf[4][2];
            #pragma unroll
            for (int tn = 0; tn < 4; tn++) {
                bf[tn][0] = __float_as_uint(Bc[(kk + qd) * BS_STRIDE + wn + tn * 8 + g]);
                bf[tn][1] = __float_as_uint(Bc[(kk + qd + 4) * BS_STRIDE + wn + tn * 8 + g]);
            }
            #pragma unroll
            for (int tm = 0; tm < 4; tm++)
                #pragma unroll
                for (int tn = 0; tn < 4; tn++)
                    mma8(acc[tm][tn][0], acc[tm][tn][1], acc[tm][tn][2], acc[tm][tn][3],
                         af[tm][0], af[tm][1], af[tm][2], af[tm][3],
                         bf[tn][0], bf[tn][1]);
        }

        // publish prefetched chunk into the other buffer; single sync
        if (more) {
            const int nxt = cur ^ 1;
            float* An = As + nxt * AS_BUF;
            float* Bn = Bs + nxt * BS_BUF;
            #pragma unroll
            for (int r = 0; r < 4; r++) {
                int idx = tid + r * 256;
                float* ap = &An[(idx >> 3) * AS_STRIDE + ((idx & 7) << 2)];
                ap[0] = t32(a_reg[r].x); ap[1] = t32(a_reg[r].y);
                ap[2] = t32(a_reg[r].z); ap[3] = t32(a_reg[r].w);
                float* bp = &Bn[(idx >> 5) * BS_STRIDE + ((idx & 31) << 2)];
                bp[0] = t32(b_reg[r].x); bp[1] = t32(b_reg[r].y);
                bp[2] = t32(b_reg[r].z); bp[3] = t32(b_reg[r].w);
            }
            __syncthreads();
            cur = nxt;
        }
    }

    // ---- epilogue: direct global float2 stores
    #pragma unroll
    for (int tm = 0; tm < 4; tm++) {
        const long row0 = bm0 + wm + tm * 16 + g;
        const long row1 = row0 + 8;
        #pragma unroll
        for (int tn = 0; tn < 4; tn++) {
            const long col = bn0 + wn + tn * 8 + 2 * qd;
            *(float2*)(C + row0 * N + col) = make_float2(acc[tm][tn][0], acc[tm][tn][1]);
            *(float2*)(C + row1 * N + col) = make_float2(acc[tm][tn][2], acc[tm][tn][3]);
        }
    }
}

// ---------------------------------------------------------------------------
// Flash attention (unchanged from R3): FA2-style register-resident tf32 mma.
// ---------------------------------------------------------------------------
static constexpr int KS_STRIDE = 76;
static constexpr int VS_STRIDE = 72;
static constexpr int PS_STRIDE = 72;

__global__ __launch_bounds__(128) void flash3(
    const float* __restrict__ Qg, const float* __restrict__ Kg,
    const float* __restrict__ Vg, float* __restrict__ Og)
{
    extern __shared__ float sm[];
    float* Ks = sm;                               // [64][76]
    float* Vs = Ks + 64 * KS_STRIDE;              // [64][72]
    float* Psb = Vs + 64 * VS_STRIDE;             // 4 x [16][72]

    const int tid = threadIdx.x;
    const int w   = tid >> 5;
    const int l   = tid & 31;
    const int g   = l >> 2;
    const int qd  = l & 3;
    const int b = blockIdx.z, h = blockIdx.y;
    const int q0 = blockIdx.x * 64;
    float* Ps = Psb + w * 16 * PS_STRIDE;

    #pragma unroll
    for (int r = 0; r < 8; r++) {
        int idx = tid + r * 128;
        int row = idx >> 4, c = (idx & 15) << 2;
        float4 v = *(const float4*)(Qg + ((long)(b * SEQ + q0 + row)) * DMODEL + h * DHEAD + c);
        Ks[row * KS_STRIDE + c + 0] = t32(v.x * 0.125f);
        Ks[row * KS_STRIDE + c + 1] = t32(v.y * 0.125f);
        Ks[row * KS_STRIDE + c + 2] = t32(v.z * 0.125f);
        Ks[row * KS_STRIDE + c + 3] = t32(v.w * 0.125f);
    }
    __syncthreads();

    uint32_t qa[8][4];
    {
        const int r0 = (w * 16 + g) * KS_STRIDE;
        const int r1 = (w * 16 + g + 8) * KS_STRIDE;
        #pragma unroll
        for (int k = 0; k < 8; k++) {
            qa[k][0] = __float_as_uint(Ks[r0 + k * 8 + qd]);
            qa[k][1] = __float_as_uint(Ks[r1 + k * 8 + qd]);
            qa[k][2] = __float_as_uint(Ks[r0 + k * 8 + qd + 4]);
            qa[k][3] = __float_as_uint(Ks[r1 + k * 8 + qd + 4]);
        }
    }

    float oacc[8][4];
    #pragma unroll
    for (int n = 0; n < 8; n++)
        #pragma unroll
        for (int e = 0; e < 4; e++) oacc[n][e] = 0.0f;
    float m0 = -1e30f, m1 = -1e30f, l0 = 0.0f, l1 = 0.0f;

    const int ntiles = blockIdx.x + 1;
    for (int t = 0; t < ntiles; t++) {
        const int k0 = t * 64;
        __syncthreads();

        #pragma unroll
        for (int r = 0; r < 8; r++) {
            int idx = tid + r * 128;
            int row = idx >> 4, c = (idx & 15) << 2;
            long base = ((long)(b * SEQ + k0 + row)) * DMODEL + h * DHEAD + c;
            float4 kv = *(const float4*)(Kg + base);
            Ks[row * KS_STRIDE + c + 0] = t32(kv.x);
            Ks[row * KS_STRIDE + c + 1] = t32(kv.y);
            Ks[row * KS_STRIDE + c + 2] = t32(kv.z);
            Ks[row * KS_STRIDE + c + 3] = t32(kv.w);
            float4 vv = *(const float4*)(Vg + base);
            Vs[row * VS_STRIDE + c + 0] = t32(vv.x);
            Vs[row * VS_STRIDE + c + 1] = t32(vv.y);
            Vs[row * VS_STRIDE + c + 2] = t32(vv.z);
            Vs[row * VS_STRIDE + c + 3] = t32(vv.w);
        }
        __syncthreads();

        float sacc[8][4];
        #pragma unroll
        for (int n = 0; n < 8; n++) {
            sacc[n][0] = sacc[n][1] = sacc[n][2] = sacc[n][3] = 0.0f;
            const int krow = (n * 8 + g) * KS_STRIDE;
            #pragma unroll
            for (int k = 0; k < 8; k++) {
                uint32_t b0 = __float_as_uint(Ks[krow + k * 8 + qd]);
                uint32_t b1 = __float_as_uint(Ks[krow + k * 8 + qd + 4]);
                mma8(sacc[n][0], sacc[n][1], sacc[n][2], sacc[n][3],
                     qa[k][0], qa[k][1], qa[k][2], qa[k][3], b0, b1);
            }
        }

        if (t == ntiles - 1) {
            const int r0 = w * 16 + g, r1 = r0 + 8;
            #pragma unroll
            for (int n = 0; n < 8; n++) {
                int c0 = n * 8 + 2 * qd, c1 = c0 + 1;
                if (c0 > r0) sacc[n][0] = -1e30f;
                if (c1 > r0) sacc[n][1] = -1e30f;
                if (c0 > r1) sacc[n][2] = -1e30f;
                if (c1 > r1) sacc[n][3] = -1e30f;
            }
        }

        float mx0 = -1e30f, mx1 = -1e30f;
        #pragma unroll
        for (int n = 0; n < 8; n++) {
            mx0 = fmaxf(mx0, fmaxf(sacc[n][0], sacc[n][1]));
            mx1 = fmaxf(mx1, fmaxf(sacc[n][2], sacc[n][3]));
        }
        mx0 = fmaxf(mx0, __shfl_xor_sync(0xffffffffu, mx0, 1));
        mx0 = fmaxf(mx0, __shfl_xor_sync(0xffffffffu, mx0, 2));
        mx1 = fmaxf(mx1, __shfl_xor_sync(0xffffffffu, mx1, 1));
        mx1 = fmaxf(mx1, __shfl_xor_sync(0xffffffffu, mx1, 2));
        const float mn0 = fmaxf(m0, mx0);
        const float mn1 = fmaxf(m1, mx1);
        const float cr0 = __expf(m0 - mn0);
        const float cr1 = __expf(m1 - mn1);

        float s0 = 0.0f, s1 = 0.0f;
        #pragma unroll
        for (int n = 0; n < 8; n++) {
            float p0 = __expf(sacc[n][0] - mn0);
            float p1 = __expf(sacc[n][1] - mn0);
            float p2 = __expf(sacc[n][2] - mn1);
            float p3 = __expf(sacc[n][3] - mn1);
            s0 += p0 + p1;
            s1 += p2 + p3;
            *(float2*)&Ps[g * PS_STRIDE + n * 8 + 2 * qd]       = make_float2(t32(p0), t32(p1));
            *(float2*)&Ps[(g + 8) * PS_STRIDE + n * 8 + 2 * qd] = make_float2(t32(p2), t32(p3));
        }
        s0 += __shfl_xor_sync(0xffffffffu, s0, 1);
        s0 += __shfl_xor_sync(0xffffffffu, s0, 2);
        s1 += __shfl_xor_sync(0xffffffffu, s1, 1);
        s1 += __shfl_xor_sync(0xffffffffu, s1, 2);
        l0 = l0 * cr0 + s0;
        l1 = l1 * cr1 + s1;
        m0 = mn0;
        m1 = mn1;

        #pragma unroll
        for (int n = 0; n < 8; n++) {
            oacc[n][0] *= cr0; oacc[n][1] *= cr0;
            oacc[n][2] *= cr1; oacc[n][3] *= cr1;
        }
        __syncwarp();

        #pragma unroll
        for (int k = 0; k < 8; k++) {
            uint32_t pa0 = __float_as_uint(Ps[g * PS_STRIDE + k * 8 + qd]);
            uint32_t pa1 = __float_as_uint(Ps[(g + 8) * PS_STRIDE + k * 8 + qd]);
            uint32_t pa2 = __float_as_uint(Ps[g * PS_STRIDE + k * 8 + qd + 4]);
            uint32_t pa3 = __float_as_uint(Ps[(g + 8) * PS_STRIDE + k * 8 + qd + 4]);
            #pragma unroll
            for (int n = 0; n < 8; n++) {
                uint32_t b0 = __float_as_uint(Vs[(k * 8 + qd) * VS_STRIDE + n * 8 + g]);
                uint32_t b1 = __float_as_uint(Vs[(k * 8 + qd + 4) * VS_STRIDE + n * 8 + g]);
                mma8(oacc[n][0], oacc[n][1], oacc[n][2], oacc[n][3],
                     pa0, pa1, pa2, pa3, b0, b1);
            }
        }
    }

    const float inv0 = 1.0f / l0;
    const float inv1 = 1.0f / l1;
    const long row0 = (long)(b * SEQ + q0 + w * 16 + g);
    const long row1 = row0 + 8;
    #pragma unroll
    for (int n = 0; n < 8; n++) {
        int c = h * DHEAD + n * 8 + 2 * qd;
        *(float2*)(Og + row0 * DMODEL + c) = make_float2(oacc[n][0] * inv0, oacc[n][1] * inv0);
        *(float2*)(Og + row1 * DMODEL + c) = make_float2(oacc[n][2] * inv1, oacc[n][3] * inv1);
    }
}

// ---------------------------------------------------------------------------
// Launch
// ---------------------------------------------------------------------------
extern "C" void kernel_launch(void* const* d_in, const int* in_sizes, int n_in,
                              void* d_out, int out_size)
{
    const float* x  = (const float*)d_in[0];
    const float* wq = (const float*)d_in[1];
    const float* wk = (const float*)d_in[2];
    const float* wv = (const float*)d_in[3];
    const float* wo = (const float*)d_in[4];
    float* out = (float*)d_out;

    float *qb, *kb, *vb, *ab;
    cudaGetSymbolAddress((void**)&qb, g_q);
    cudaGetSymbolAddress((void**)&kb, g_k);
    cudaGetSymbolAddress((void**)&vb, g_v);
    cudaGetSymbolAddress((void**)&ab, g_att);

    cudaFuncSetAttribute(gemm_raw<3>, cudaFuncAttributeMaxDynamicSharedMemorySize, GEMM_SMEM);
    cudaFuncSetAttribute(gemm_raw<1>, cudaFuncAttributeMaxDynamicSharedMemorySize, GEMM_SMEM);

    // Fused QKV projection: one launch, blockIdx.z selects {W,C}.
    dim3 gq(DMODEL / 128, MROWS / 128, 3);   // (8, 64, 3)
    gemm_raw<3><<<gq, 256, GEMM_SMEM>>>(x, wq, wk, wv, qb, kb, vb, MROWS, DMODEL, DMODEL);

    const int fl_smem = (64 * KS_STRIDE + 64 * VS_STRIDE + 4 * 16 * PS_STRIDE) * (int)sizeof(float);
    cudaFuncSetAttribute(flash3, cudaFuncAttributeMaxDynamicSharedMemorySize, fl_smem);
    dim3 fg(SEQ / 64, NHEAD, BATCH);         // (32, 16, 4)
    flash3<<<fg, 128, fl_smem>>>(qb, kb, vb, ab);

    dim3 go(DMODEL / 128, MROWS / 128, 1);   // (8, 64)
    gemm_raw<1><<<go, 256, GEMM_SMEM>>>(ab, wo, nullptr, nullptr, out, nullptr, nullptr,
                                        MROWS, DMODEL, DMODEL);
}

// round 6
// speedup vs baseline: 4.3104x; 1.2088x over previous
#include <cuda_runtime.h>
#include <mma.h>
#include <cstddef>
#include <cstdint>

using namespace nvcuda;

// Problem constants
static constexpr int BATCH  = 4;
static constexpr int SEQ    = 2048;
static constexpr int DMODEL = 1024;
static constexpr int NHEAD  = 16;
static constexpr int DHEAD  = 64;
static constexpr int MROWS  = BATCH * SEQ;   // 8192

// Scratch (device globals — no allocations allowed)
__device__ float g_q[MROWS * DMODEL];
__device__ float g_k[MROWS * DMODEL];
__device__ float g_v[MROWS * DMODEL];
__device__ float g_att[MROWS * DMODEL];
__device__ float g_xr[MROWS * DMODEL];          // tf32-rounded x
__device__ float g_wr[4 * DMODEL * DMODEL];     // tf32-rounded W_Q,W_K,W_V,W_O

__device__ __forceinline__ float t32(float x) { return wmma::__float_to_tf32(x); }

// mma.m16n8k8 tf32, row.col, fp32 accumulate.
__device__ __forceinline__ void mma8(float& c0, float& c1, float& c2, float& c3,
                                     uint32_t a0, uint32_t a1, uint32_t a2, uint32_t a3,
                                     uint32_t b0, uint32_t b1)
{
    asm volatile(
        "mma.sync.aligned.m16n8k8.row.col.f32.tf32.tf32.f32 "
        "{%0,%1,%2,%3}, {%4,%5,%6,%7}, {%8,%9}, {%0,%1,%2,%3};\n"
        : "+f"(c0), "+f"(c1), "+f"(c2), "+f"(c3)
        : "r"(a0), "r"(a1), "r"(a2), "r"(a3), "r"(b0), "r"(b1));
}

__device__ __forceinline__ void cp16(void* smem_dst, const void* gsrc) {
    uint32_t s = (uint32_t)__cvta_generic_to_shared(smem_dst);
    asm volatile("cp.async.cg.shared.global [%0], [%1], 16;\n" :: "r"(s), "l"(gsrc));
}
__device__ __forceinline__ void cp_commit() { asm volatile("cp.async.commit_group;\n"); }
template <int N>
__device__ __forceinline__ void cp_wait() { asm volatile("cp.async.wait_group %0;\n" :: "n"(N)); }

// ---------------------------------------------------------------------------
// Elementwise tf32 RN rounding pass (inputs pre-rounded once per call).
// ---------------------------------------------------------------------------
__global__ __launch_bounds__(256) void round_tf32(const float* __restrict__ in,
                                                  float* __restrict__ out, int n4)
{
    int i = blockIdx.x * 256 + threadIdx.x;
    if (i < n4) {
        float4 v = ((const float4*)in)[i];
        v.x = t32(v.x); v.y = t32(v.y); v.z = t32(v.z); v.w = t32(v.w);
        ((float4*)out)[i] = v;
    }
}

// ---------------------------------------------------------------------------
// Raw-mma TF32 GEMM, cp.async double-buffered. Inputs MUST be tf32-rounded.
// C[M,N] = A[M,K]*B[K,N]. 128x128x32 tile, 256 thr = 8 warps, warp 64x32.
// Strides: A 36 (conflict-free), B 136 (conflict-free). 2 CTAs/SM.
// ROUND: round outputs to tf32 (for tensors feeding later tf32 consumers).
// ---------------------------------------------------------------------------
static constexpr int AS_STRIDE = 36;
static constexpr int BS_STRIDE = 136;
static constexpr int AS_BUF = 128 * AS_STRIDE;   // 4608 floats
static constexpr int BS_BUF = 32 * BS_STRIDE;    // 4352 floats
static constexpr int GEMM_SMEM = (2 * AS_BUF + 2 * BS_BUF) * (int)sizeof(float); // 71680 B

template <int NMAT, bool ROUND>
__global__ __launch_bounds__(256, 2) void gemm_cp(
    const float* __restrict__ A,
    const float* __restrict__ B0, const float* __restrict__ B1, const float* __restrict__ B2,
    float* __restrict__ C0, float* __restrict__ C1, float* __restrict__ C2,
    int M, int N, int K)
{
    extern __shared__ float smem[];
    float* As = smem;                 // [2][128][36]
    float* Bs = smem + 2 * AS_BUF;    // [2][32][136]

    const float* B = B0;
    float* C = C0;
    if (NMAT > 1) {
        if (blockIdx.z == 1) { B = B1; C = C1; }
        else if (blockIdx.z == 2) { B = B2; C = C2; }
    }

    const int tid = threadIdx.x;
    const int wid = tid >> 5;
    const int l   = tid & 31;
    const int g   = l >> 2;
    const int qd  = l & 3;
    const int wm  = (wid & 1) * 64;
    const int wn  = (wid >> 1) * 32;
    const long bm0 = (long)blockIdx.y * 128;
    const long bn0 = (long)blockIdx.x * 128;

    // per-thread cp.async assignments (4 x 16B for A, 4 x 16B for B per chunk)
    const int a_row[2] = { tid >> 3, (tid + 256) >> 3 };   // pattern repeats +512
    const int a_col = (tid & 7) << 2;
    const int b_col = (tid & 31) << 2;

    float acc[4][4][4];
    #pragma unroll
    for (int i = 0; i < 4; i++)
        #pragma unroll
        for (int j = 0; j < 4; j++)
            #pragma unroll
            for (int e = 0; e < 4; e++) acc[i][j][e] = 0.0f;

    // ---- prologue: chunk 0 -> buf 0 via cp.async
    #pragma unroll
    for (int r = 0; r < 4; r++) {
        int idx = tid + r * 256;
        int ar = idx >> 3, ac = (idx & 7) << 2;
        cp16(&As[ar * AS_STRIDE + ac], A + (bm0 + ar) * (long)K + ac);
        int br = idx >> 5, bc = (idx & 31) << 2;
        cp16(&Bs[br * BS_STRIDE + bc], B + (long)br * N + bn0 + bc);
    }
    cp_commit();
    cp_wait<0>();
    __syncthreads();

    int cur = 0;
    for (int k0 = 32; k0 <= K; k0 += 32) {
        const bool more = (k0 < K);
        // issue next chunk into the other buffer (overlaps with compute)
        if (more) {
            const int nxt = cur ^ 1;
            float* An = As + nxt * AS_BUF;
            float* Bn = Bs + nxt * BS_BUF;
            #pragma unroll
            for (int r = 0; r < 4; r++) {
                int idx = tid + r * 256;
                int ar = idx >> 3, ac = (idx & 7) << 2;
                cp16(&An[ar * AS_STRIDE + ac], A + (bm0 + ar) * (long)K + k0 + ac);
                int br = idx >> 5, bc = (idx & 31) << 2;
                cp16(&Bn[br * BS_STRIDE + bc], B + (long)(k0 + br) * N + bn0 + bc);
            }
            cp_commit();
        }

        // compute current chunk
        const float* Ac = As + cur * AS_BUF;
        const float* Bc = Bs + cur * BS_BUF;
        #pragma unroll
        for (int kk = 0; kk < 32; kk += 8) {
            uint32_t af[4][4];
            #pragma unroll
            for (int tm = 0; tm < 4; tm++) {
                const int r0 = (wm + tm * 16 + g) * AS_STRIDE + kk;
                const int r1 = r0 + 8 * AS_STRIDE;
                af[tm][0] = __float_as_uint(Ac[r0 + qd]);
                af[tm][1] = __float_as_uint(Ac[r1 + qd]);
                af[tm][2] = __float_as_uint(Ac[r0 + qd + 4]);
                af[tm][3] = __float_as_uint(Ac[r1 + qd + 4]);
            }
            uint32_t bf[4][2];
            #pragma unroll
            for (int tn = 0; tn < 4; tn++) {
                bf[tn][0] = __float_as_uint(Bc[(kk + qd) * BS_STRIDE + wn + tn * 8 + g]);
                bf[tn][1] = __float_as_uint(Bc[(kk + qd + 4) * BS_STRIDE + wn + tn * 8 + g]);
            }
            #pragma unroll
            for (int tm = 0; tm < 4; tm++)
                #pragma unroll
                for (int tn = 0; tn < 4; tn++)
                    mma8(acc[tm][tn][0], acc[tm][tn][1], acc[tm][tn][2], acc[tm][tn][3],
                         af[tm][0], af[tm][1], af[tm][2], af[tm][3],
                         bf[tn][0], bf[tn][1]);
        }

        if (more) {
            cp_wait<0>();
            __syncthreads();
            cur ^= 1;
        }
    }

    // ---- epilogue
    #pragma unroll
    for (int tm = 0; tm < 4; tm++) {
        const long row0 = bm0 + wm + tm * 16 + g;
        const long row1 = row0 + 8;
        #pragma unroll
        for (int tn = 0; tn < 4; tn++) {
            const long col = bn0 + wn + tn * 8 + 2 * qd;
            float v0 = acc[tm][tn][0], v1 = acc[tm][tn][1];
            float v2 = acc[tm][tn][2], v3 = acc[tm][tn][3];
            if (ROUND) { v0 = t32(v0); v1 = t32(v1); v2 = t32(v2); v3 = t32(v3); }
            *(float2*)(C + row0 * N + col) = make_float2(v0, v1);
            *(float2*)(C + row1 * N + col) = make_float2(v2, v3);
        }
    }
}

// ---------------------------------------------------------------------------
// Flash attention, FA2-style register-resident tf32 mma. Q/K/V arrive
// tf32-rounded (GEMM epilogue), so staging is raw copy (cp.async for K/V).
// Epilogue writes tf32-rounded output (feeds the O-projection GEMM).
// ---------------------------------------------------------------------------
static constexpr int KS_STRIDE = 76;
static constexpr int VS_STRIDE = 72;
static constexpr int PS_STRIDE = 72;

__global__ __launch_bounds__(128) void flash4(
    const float* __restrict__ Qg, const float* __restrict__ Kg,
    const float* __restrict__ Vg, float* __restrict__ Og)
{
    extern __shared__ float sm[];
    float* Ks = sm;                               // [64][76]
    float* Vs = Ks + 64 * KS_STRIDE;              // [64][72]
    float* Psb = Vs + 64 * VS_STRIDE;             // 4 x [16][72]

    const int tid = threadIdx.x;
    const int w   = tid >> 5;
    const int l   = tid & 31;
    const int g   = l >> 2;
    const int qd  = l & 3;
    const int b = blockIdx.z, h = blockIdx.y;
    const int q0 = blockIdx.x * 64;
    float* Ps = Psb + w * 16 * PS_STRIDE;

    // Stage Q (x0.125 exact scale; input already tf32) into Ks, pull to regs
    #pragma unroll
    for (int r = 0; r < 8; r++) {
        int idx = tid + r * 128;
        int row = idx >> 4, c = (idx & 15) << 2;
        float4 v = *(const float4*)(Qg + ((long)(b * SEQ + q0 + row)) * DMODEL + h * DHEAD + c);
        Ks[row * KS_STRIDE + c + 0] = v.x * 0.125f;
        Ks[row * KS_STRIDE + c + 1] = v.y * 0.125f;
        Ks[row * KS_STRIDE + c + 2] = v.z * 0.125f;
        Ks[row * KS_STRIDE + c + 3] = v.w * 0.125f;
    }
    __syncthreads();

    uint32_t qa[8][4];
    {
        const int r0 = (w * 16 + g) * KS_STRIDE;
        const int r1 = (w * 16 + g + 8) * KS_STRIDE;
        #pragma unroll
        for (int k = 0; k < 8; k++) {
            qa[k][0] = __float_as_uint(Ks[r0 + k * 8 + qd]);
            qa[k][1] = __float_as_uint(Ks[r1 + k * 8 + qd]);
            qa[k][2] = __float_as_uint(Ks[r0 + k * 8 + qd + 4]);
            qa[k][3] = __float_as_uint(Ks[r1 + k * 8 + qd + 4]);
        }
    }

    float oacc[8][4];
    #pragma unroll
    for (int n = 0; n < 8; n++)
        #pragma unroll
        for (int e = 0; e < 4; e++) oacc[n][e] = 0.0f;
    float m0 = -1e30f, m1 = -1e30f, l0 = 0.0f, l1 = 0.0f;

    const int ntiles = blockIdx.x + 1;
    for (int t = 0; t < ntiles; t++) {
        const int k0 = t * 64;
        __syncthreads();   // prior tile's consumers done (incl. Q frag reads)

        // K/V tile via cp.async (values already tf32)
        #pragma unroll
        for (int r = 0; r < 8; r++) {
            int idx = tid + r * 128;
            int row = idx >> 4, c = (idx & 15) << 2;
            long base = ((long)(b * SEQ + k0 + row)) * DMODEL + h * DHEAD + c;
            cp16(&Ks[row * KS_STRIDE + c], Kg + base);
            cp16(&Vs[row * VS_STRIDE + c], Vg + base);
        }
        cp_commit();
        cp_wait<0>();
        __syncthreads();

        float sacc[8][4];
        #pragma unroll
        for (int n = 0; n < 8; n++) {
            sacc[n][0] = sacc[n][1] = sacc[n][2] = sacc[n][3] = 0.0f;
            const int krow = (n * 8 + g) * KS_STRIDE;
            #pragma unroll
            for (int k = 0; k < 8; k++) {
                uint32_t b0 = __float_as_uint(Ks[krow + k * 8 + qd]);
                uint32_t b1 = __float_as_uint(Ks[krow + k * 8 + qd + 4]);
                mma8(sacc[n][0], sacc[n][1], sacc[n][2], sacc[n][3],
                     qa[k][0], qa[k][1], qa[k][2], qa[k][3], b0, b1);
            }
        }

        if (t == ntiles - 1) {
            const int r0 = w * 16 + g, r1 = r0 + 8;
            #pragma unroll
            for (int n = 0; n < 8; n++) {
                int c0 = n * 8 + 2 * qd, c1 = c0 + 1;
                if (c0 > r0) sacc[n][0] = -1e30f;
                if (c1 > r0) sacc[n][1] = -1e30f;
                if (c0 > r1) sacc[n][2] = -1e30f;
                if (c1 > r1) sacc[n][3] = -1e30f;
            }
        }

        float mx0 = -1e30f, mx1 = -1e30f;
        #pragma unroll
        for (int n = 0; n < 8; n++) {
            mx0 = fmaxf(mx0, fmaxf(sacc[n][0], sacc[n][1]));
            mx1 = fmaxf(mx1, fmaxf(sacc[n][2], sacc[n][3]));
        }
        mx0 = fmaxf(mx0, __shfl_xor_sync(0xffffffffu, mx0, 1));
        mx0 = fmaxf(mx0, __shfl_xor_sync(0xffffffffu, mx0, 2));
        mx1 = fmaxf(mx1, __shfl_xor_sync(0xffffffffu, mx1, 1));
        mx1 = fmaxf(mx1, __shfl_xor_sync(0xffffffffu, mx1, 2));
        const float mn0 = fmaxf(m0, mx0);
        const float mn1 = fmaxf(m1, mx1);
        const float cr0 = __expf(m0 - mn0);
        const float cr1 = __expf(m1 - mn1);

        float s0 = 0.0f, s1 = 0.0f;
        #pragma unroll
        for (int n = 0; n < 8; n++) {
            float p0 = __expf(sacc[n][0] - mn0);
            float p1 = __expf(sacc[n][1] - mn0);
            float p2 = __expf(sacc[n][2] - mn1);
            float p3 = __expf(sacc[n][3] - mn1);
            s0 += p0 + p1;
            s1 += p2 + p3;
            *(float2*)&Ps[g * PS_STRIDE + n * 8 + 2 * qd]       = make_float2(t32(p0), t32(p1));
            *(float2*)&Ps[(g + 8) * PS_STRIDE + n * 8 + 2 * qd] = make_float2(t32(p2), t32(p3));
        }
        s0 += __shfl_xor_sync(0xffffffffu, s0, 1);
        s0 += __shfl_xor_sync(0xffffffffu, s0, 2);
        s1 += __shfl_xor_sync(0xffffffffu, s1, 1);
        s1 += __shfl_xor_sync(0xffffffffu, s1, 2);
        l0 = l0 * cr0 + s0;
        l1 = l1 * cr1 + s1;
        m0 = mn0;
        m1 = mn1;

        #pragma unroll
        for (int n = 0; n < 8; n++) {
            oacc[n][0] *= cr0; oacc[n][1] *= cr0;
            oacc[n][2] *= cr1; oacc[n][3] *= cr1;
        }
        __syncwarp();

        #pragma unroll
        for (int k = 0; k < 8; k++) {
            uint32_t pa0 = __float_as_uint(Ps[g * PS_STRIDE + k * 8 + qd]);
            uint32_t pa1 = __float_as_uint(Ps[(g + 8) * PS_STRIDE + k * 8 + qd]);
            uint32_t pa2 = __float_as_uint(Ps[g * PS_STRIDE + k * 8 + qd + 4]);
            uint32_t pa3 = __float_as_uint(Ps[(g + 8) * PS_STRIDE + k * 8 + qd + 4]);
            #pragma unroll
            for (int n = 0; n < 8; n++) {
                uint32_t b0 = __float_as_uint(Vs[(k * 8 + qd) * VS_STRIDE + n * 8 + g]);
                uint32_t b1 = __float_as_uint(Vs[(k * 8 + qd + 4) * VS_STRIDE + n * 8 + g]);
                mma8(oacc[n][0], oacc[n][1], oacc[n][2], oacc[n][3],
                     pa0, pa1, pa2, pa3, b0, b1);
            }
        }
    }

    // Epilogue: normalize, tf32-round (O-proj GEMM consumes via cp.async)
    const float inv0 = 1.0f / l0;
    const float inv1 = 1.0f / l1;
    const long row0 = (long)(b * SEQ + q0 + w * 16 + g);
    const long row1 = row0 + 8;
    #pragma unroll
    for (int n = 0; n < 8; n++) {
        int c = h * DHEAD + n * 8 + 2 * qd;
        *(float2*)(Og + row0 * DMODEL + c) = make_float2(t32(oacc[n][0] * inv0), t32(oacc[n][1] * inv0));
        *(float2*)(Og + row1 * DMODEL + c) = make_float2(t32(oacc[n][2] * inv1), t32(oacc[n][3] * inv1));
    }
}

// ---------------------------------------------------------------------------
// Launch
// ---------------------------------------------------------------------------
extern "C" void kernel_launch(void* const* d_in, const int* in_sizes, int n_in,
                              void* d_out, int out_size)
{
    const float* x  = (const float*)d_in[0];
    const float* wq = (const float*)d_in[1];
    const float* wk = (const float*)d_in[2];
    const float* wv = (const float*)d_in[3];
    const float* wo = (const float*)d_in[4];
    float* out = (float*)d_out;

    float *qb, *kb, *vb, *ab, *xr, *wr;
    cudaGetSymbolAddress((void**)&qb, g_q);
    cudaGetSymbolAddress((void**)&kb, g_k);
    cudaGetSymbolAddress((void**)&vb, g_v);
    cudaGetSymbolAddress((void**)&ab, g_att);
    cudaGetSymbolAddress((void**)&xr, g_xr);
    cudaGetSymbolAddress((void**)&wr, g_wr);

    float* wqr = wr;
    float* wkr = wr + (size_t)DMODEL * DMODEL;
    float* wvr = wr + 2 * (size_t)DMODEL * DMODEL;
    float* wor = wr + 3 * (size_t)DMODEL * DMODEL;

    // Pre-round inputs to tf32 (RN), once per call
    const int NX4 = MROWS * DMODEL / 4;
    const int NW4 = DMODEL * DMODEL / 4;
    round_tf32<<<(NX4 + 255) / 256, 256>>>(x,  xr,  NX4);
    round_tf32<<<(NW4 + 255) / 256, 256>>>(wq, wqr, NW4);
    round_tf32<<<(NW4 + 255) / 256, 256>>>(wk, wkr, NW4);
    round_tf32<<<(NW4 + 255) / 256, 256>>>(wv, wvr, NW4);
    round_tf32<<<(NW4 + 255) / 256, 256>>>(wo, wor, NW4);

    cudaFuncSetAttribute((const void*)gemm_cp<3, true>, cudaFuncAttributeMaxDynamicSharedMemorySize, GEMM_SMEM);
    cudaFuncSetAttribute((const void*)gemm_cp<1, false>, cudaFuncAttributeMaxDynamicSharedMemorySize, GEMM_SMEM);

    // Fused QKV projection (outputs tf32-rounded for flash)
    dim3 gq(DMODEL / 128, MROWS / 128, 3);   // (8, 64, 3)
    gemm_cp<3, true><<<gq, 256, GEMM_SMEM>>>(xr, wqr, wkr, wvr, qb, kb, vb, MROWS, DMODEL, DMODEL);

    const int fl_smem = (64 * KS_STRIDE + 64 * VS_STRIDE + 4 * 16 * PS_STRIDE) * (int)sizeof(float);
    cudaFuncSetAttribute(flash4, cudaFuncAttributeMaxDynamicSharedMemorySize, fl_smem);
    dim3 fg(SEQ / 64, NHEAD, BATCH);         // (32, 16, 4)
    flash4<<<fg, 128, fl_smem>>>(qb, kb, vb, ab);

    // Output projection (full-precision output)
    dim3 go(DMODEL / 128, MROWS / 128, 1);   // (8, 64)
    gemm_cp<1, false><<<go, 256, GEMM_SMEM>>>(ab, wor, nullptr, nullptr, out, nullptr, nullptr,
                                              MROWS, DMODEL, DMODEL);
}

// round 7
// speedup vs baseline: 4.3322x; 1.0051x over previous
#include <cuda_runtime.h>
#include <mma.h>
#include <cstddef>
#include <cstdint>

using namespace nvcuda;

// Problem constants
static constexpr int BATCH  = 4;
static constexpr int SEQ    = 2048;
static constexpr int DMODEL = 1024;
static constexpr int NHEAD  = 16;
static constexpr int DHEAD  = 64;
static constexpr int MROWS  = BATCH * SEQ;   // 8192

// Scratch (device globals — no allocations allowed)
__device__ float g_q[MROWS * DMODEL];
__device__ float g_k[MROWS * DMODEL];
__device__ float g_v[MROWS * DMODEL];
__device__ float g_att[MROWS * DMODEL];
__device__ float g_xr[MROWS * DMODEL];          // tf32-rounded x
__device__ float g_wr[4 * DMODEL * DMODEL];     // tf32-rounded W_Q,W_K,W_V,W_O

__device__ __forceinline__ float t32(float x) { return wmma::__float_to_tf32(x); }

// mma.m16n8k8 tf32, row.col, fp32 accumulate.
__device__ __forceinline__ void mma8(float& c0, float& c1, float& c2, float& c3,
                                     uint32_t a0, uint32_t a1, uint32_t a2, uint32_t a3,
                                     uint32_t b0, uint32_t b1)
{
    asm volatile(
        "mma.sync.aligned.m16n8k8.row.col.f32.tf32.tf32.f32 "
        "{%0,%1,%2,%3}, {%4,%5,%6,%7}, {%8,%9}, {%0,%1,%2,%3};\n"
        : "+f"(c0), "+f"(c1), "+f"(c2), "+f"(c3)
        : "r"(a0), "r"(a1), "r"(a2), "r"(a3), "r"(b0), "r"(b1));
}

__device__ __forceinline__ void cp16(void* smem_dst, const void* gsrc) {
    uint32_t s = (uint32_t)__cvta_generic_to_shared(smem_dst);
    asm volatile("cp.async.cg.shared.global [%0], [%1], 16;\n" :: "r"(s), "l"(gsrc));
}
__device__ __forceinline__ void cp_commit() { asm volatile("cp.async.commit_group;\n"); }
template <int N>
__device__ __forceinline__ void cp_wait() { asm volatile("cp.async.wait_group %0;\n" :: "n"(N)); }

// ---------------------------------------------------------------------------
// Elementwise tf32 RN rounding pass.
// ---------------------------------------------------------------------------
__global__ __launch_bounds__(256) void round_tf32(const float* __restrict__ in,
                                                  float* __restrict__ out, int n4)
{
    int i = blockIdx.x * 256 + threadIdx.x;
    if (i < n4) {
        float4 v = ((const float4*)in)[i];
        v.x = t32(v.x); v.y = t32(v.y); v.z = t32(v.z); v.w = t32(v.w);
        ((float4*)out)[i] = v;
    }
}

// ---------------------------------------------------------------------------
// Raw-mma TF32 GEMM, cp.async double-buffered. Inputs MUST be tf32-rounded.
// (unchanged from R6)
// ---------------------------------------------------------------------------
static constexpr int AS_STRIDE = 36;
static constexpr int BS_STRIDE = 136;
static constexpr int AS_BUF = 128 * AS_STRIDE;
static constexpr int BS_BUF = 32 * BS_STRIDE;
static constexpr int GEMM_SMEM = (2 * AS_BUF + 2 * BS_BUF) * (int)sizeof(float); // 71680 B

template <int NMAT, bool ROUND>
__global__ __launch_bounds__(256, 2) void gemm_cp(
    const float* __restrict__ A,
    const float* __restrict__ B0, const float* __restrict__ B1, const float* __restrict__ B2,
    float* __restrict__ C0, float* __restrict__ C1, float* __restrict__ C2,
    int M, int N, int K)
{
    extern __shared__ float smem[];
    float* As = smem;
    float* Bs = smem + 2 * AS_BUF;

    const float* B = B0;
    float* C = C0;
    if (NMAT > 1) {
        if (blockIdx.z == 1) { B = B1; C = C1; }
        else if (blockIdx.z == 2) { B = B2; C = C2; }
    }

    const int tid = threadIdx.x;
    const int wid = tid >> 5;
    const int l   = tid & 31;
    const int g   = l >> 2;
    const int qd  = l & 3;
    const int wm  = (wid & 1) * 64;
    const int wn  = (wid >> 1) * 32;
    const long bm0 = (long)blockIdx.y * 128;
    const long bn0 = (long)blockIdx.x * 128;

    float acc[4][4][4];
    #pragma unroll
    for (int i = 0; i < 4; i++)
        #pragma unroll
        for (int j = 0; j < 4; j++)
            #pragma unroll
            for (int e = 0; e < 4; e++) acc[i][j][e] = 0.0f;

    #pragma unroll
    for (int r = 0; r < 4; r++) {
        int idx = tid + r * 256;
        int ar = idx >> 3, ac = (idx & 7) << 2;
        cp16(&As[ar * AS_STRIDE + ac], A + (bm0 + ar) * (long)K + ac);
        int br = idx >> 5, bc = (idx & 31) << 2;
        cp16(&Bs[br * BS_STRIDE + bc], B + (long)br * N + bn0 + bc);
    }
    cp_commit();
    cp_wait<0>();
    __syncthreads();

    int cur = 0;
    for (int k0 = 32; k0 <= K; k0 += 32) {
        const bool more = (k0 < K);
        if (more) {
            const int nxt = cur ^ 1;
            float* An = As + nxt * AS_BUF;
            float* Bn = Bs + nxt * BS_BUF;
            #pragma unroll
            for (int r = 0; r < 4; r++) {
                int idx = tid + r * 256;
                int ar = idx >> 3, ac = (idx & 7) << 2;
                cp16(&An[ar * AS_STRIDE + ac], A + (bm0 + ar) * (long)K + k0 + ac);
                int br = idx >> 5, bc = (idx & 31) << 2;
                cp16(&Bn[br * BS_STRIDE + bc], B + (long)(k0 + br) * N + bn0 + bc);
            }
            cp_commit();
        }

        const float* Ac = As + cur * AS_BUF;
        const float* Bc = Bs + cur * BS_BUF;
        #pragma unroll
        for (int kk = 0; kk < 32; kk += 8) {
            uint32_t af[4][4];
            #pragma unroll
            for (int tm = 0; tm < 4; tm++) {
                const int r0 = (wm + tm * 16 + g) * AS_STRIDE + kk;
                const int r1 = r0 + 8 * AS_STRIDE;
                af[tm][0] = __float_as_uint(Ac[r0 + qd]);
                af[tm][1] = __float_as_uint(Ac[r1 + qd]);
                af[tm][2] = __float_as_uint(Ac[r0 + qd + 4]);
                af[tm][3] = __float_as_uint(Ac[r1 + qd + 4]);
            }
            uint32_t bf[4][2];
            #pragma unroll
            for (int tn = 0; tn < 4; tn++) {
                bf[tn][0] = __float_as_uint(Bc[(kk + qd) * BS_STRIDE + wn + tn * 8 + g]);
                bf[tn][1] = __float_as_uint(Bc[(kk + qd + 4) * BS_STRIDE + wn + tn * 8 + g]);
            }
            #pragma unroll
            for (int tm = 0; tm < 4; tm++)
                #pragma unroll
                for (int tn = 0; tn < 4; tn++)
                    mma8(acc[tm][tn][0], acc[tm][tn][1], acc[tm][tn][2], acc[tm][tn][3],
                         af[tm][0], af[tm][1], af[tm][2], af[tm][3],
                         bf[tn][0], bf[tn][1]);
        }

        if (more) {
            cp_wait<0>();
            __syncthreads();
            cur ^= 1;
        }
    }

    #pragma unroll
    for (int tm = 0; tm < 4; tm++) {
        const long row0 = bm0 + wm + tm * 16 + g;
        const long row1 = row0 + 8;
        #pragma unroll
        for (int tn = 0; tn < 4; tn++) {
            const long col = bn0 + wn + tn * 8 + 2 * qd;
            float v0 = acc[tm][tn][0], v1 = acc[tm][tn][1];
            float v2 = acc[tm][tn][2], v3 = acc[tm][tn][3];
            if (ROUND) { v0 = t32(v0); v1 = t32(v1); v2 = t32(v2); v3 = t32(v3); }
            *(float2*)(C + row0 * N + col) = make_float2(v0, v1);
            *(float2*)(C + row1 * N + col) = make_float2(v2, v3);
        }
    }
}

// ---------------------------------------------------------------------------
// Flash attention v5: FA2-style register-resident tf32 mma + DOUBLE-BUFFERED
// K/V tiles via cp.async (tile t+1 in flight during compute of tile t).
// Q/K/V arrive tf32-rounded. Output tf32-rounded (feeds O-proj GEMM).
// ---------------------------------------------------------------------------
static constexpr int KS_STRIDE = 76;
static constexpr int VS_STRIDE = 72;
static constexpr int PS_STRIDE = 72;
static constexpr int KBUF = 64 * KS_STRIDE;   // 4864 floats
static constexpr int VBUF = 64 * VS_STRIDE;   // 4608 floats
static constexpr int FL_SMEM = (2 * KBUF + 2 * VBUF + 4 * 16 * PS_STRIDE) * (int)sizeof(float); // 94208 B

__global__ __launch_bounds__(128, 2) void flash5(
    const float* __restrict__ Qg, const float* __restrict__ Kg,
    const float* __restrict__ Vg, float* __restrict__ Og)
{
    extern __shared__ float sm[];
    float* Ksb = sm;                              // [2][64][76]
    float* Vsb = sm + 2 * KBUF;                   // [2][64][72]
    float* Psb = Vsb + 2 * VBUF;                  // 4 x [16][72]

    const int tid = threadIdx.x;
    const int w   = tid >> 5;
    const int l   = tid & 31;
    const int g   = l >> 2;
    const int qd  = l & 3;
    const int b = blockIdx.z, h = blockIdx.y;
    const int q0 = blockIdx.x * 64;
    float* Ps = Psb + w * 16 * PS_STRIDE;

    // ---- Stage Q (x0.125 exact scale) into Ks buffer 0, pull frags to regs
    #pragma unroll
    for (int r = 0; r < 8; r++) {
        int idx = tid + r * 128;
        int row = idx >> 4, c = (idx & 15) << 2;
        float4 v = *(const float4*)(Qg + ((long)(b * SEQ + q0 + row)) * DMODEL + h * DHEAD + c);
        Ksb[row * KS_STRIDE + c + 0] = v.x * 0.125f;
        Ksb[row * KS_STRIDE + c + 1] = v.y * 0.125f;
        Ksb[row * KS_STRIDE + c + 2] = v.z * 0.125f;
        Ksb[row * KS_STRIDE + c + 3] = v.w * 0.125f;
    }
    __syncthreads();

    uint32_t qa[8][4];
    {
        const int r0 = (w * 16 + g) * KS_STRIDE;
        const int r1 = (w * 16 + g + 8) * KS_STRIDE;
        #pragma unroll
        for (int k = 0; k < 8; k++) {
            qa[k][0] = __float_as_uint(Ksb[r0 + k * 8 + qd]);
            qa[k][1] = __float_as_uint(Ksb[r1 + k * 8 + qd]);
            qa[k][2] = __float_as_uint(Ksb[r0 + k * 8 + qd + 4]);
            qa[k][3] = __float_as_uint(Ksb[r1 + k * 8 + qd + 4]);
        }
    }
    __syncthreads();   // all Q-frag reads done before cp.async overwrites buf 0

    float oacc[8][4];
    #pragma unroll
    for (int n = 0; n < 8; n++)
        #pragma unroll
        for (int e = 0; e < 4; e++) oacc[n][e] = 0.0f;
    float m0 = -1e30f, m1 = -1e30f, l0 = 0.0f, l1 = 0.0f;

    const int ntiles = blockIdx.x + 1;
    const long bh_base = (long)b * SEQ * DMODEL + h * DHEAD;

    // thread's load coords (8 x 16B per tensor per tile)
    // prologue: tile 0 -> buffer 0
    {
        #pragma unroll
        for (int r = 0; r < 8; r++) {
            int idx = tid + r * 128;
            int row = idx >> 4, c = (idx & 15) << 2;
            long base = bh_base + (long)row * DMODEL + c;
            cp16(&Ksb[row * KS_STRIDE + c], Kg + base);
            cp16(&Vsb[row * VS_STRIDE + c], Vg + base);
        }
        cp_commit();
    }

    for (int t = 0; t < ntiles; t++) {
        const int cur = t & 1;
        // issue tile t+1 into the other buffer
        if (t + 1 < ntiles) {
            const int nxt = cur ^ 1;
            float* Kn = Ksb + nxt * KBUF;
            float* Vn = Vsb + nxt * VBUF;
            const long tbase = bh_base + (long)(t + 1) * 64 * DMODEL;
            #pragma unroll
            for (int r = 0; r < 8; r++) {
                int idx = tid + r * 128;
                int row = idx >> 4, c = (idx & 15) << 2;
                long base = tbase + (long)row * DMODEL + c;
                cp16(&Kn[row * KS_STRIDE + c], Kg + base);
                cp16(&Vn[row * VS_STRIDE + c], Vg + base);
            }
            cp_commit();
            cp_wait<1>();   // tile t's group complete
        } else {
            cp_wait<0>();
        }
        __syncthreads();

        const float* Ks = Ksb + cur * KBUF;
        const float* Vs = Vsb + cur * VBUF;

        // ---- S = Q * K^T
        float sacc[8][4];
        #pragma unroll
        for (int n = 0; n < 8; n++) {
            sacc[n][0] = sacc[n][1] = sacc[n][2] = sacc[n][3] = 0.0f;
            const int krow = (n * 8 + g) * KS_STRIDE;
            #pragma unroll
            for (int k = 0; k < 8; k++) {
                uint32_t b0 = __float_as_uint(Ks[krow + k * 8 + qd]);
                uint32_t b1 = __float_as_uint(Ks[krow + k * 8 + qd + 4]);
                mma8(sacc[n][0], sacc[n][1], sacc[n][2], sacc[n][3],
                     qa[k][0], qa[k][1], qa[k][2], qa[k][3], b0, b1);
            }
        }

        if (t == ntiles - 1) {
            const int r0 = w * 16 + g, r1 = r0 + 8;
            #pragma unroll
            for (int n = 0; n < 8; n++) {
                int c0 = n * 8 + 2 * qd, c1 = c0 + 1;
                if (c0 > r0) sacc[n][0] = -1e30f;
                if (c1 > r0) sacc[n][1] = -1e30f;
                if (c0 > r1) sacc[n][2] = -1e30f;
                if (c1 > r1) sacc[n][3] = -1e30f;
            }
        }

        // ---- online softmax (registers; quad shfl)
        float mx0 = -1e30f, mx1 = -1e30f;
        #pragma unroll
        for (int n = 0; n < 8; n++) {
            mx0 = fmaxf(mx0, fmaxf(sacc[n][0], sacc[n][1]));
            mx1 = fmaxf(mx1, fmaxf(sacc[n][2], sacc[n][3]));
        }
        mx0 = fmaxf(mx0, __shfl_xor_sync(0xffffffffu, mx0, 1));
        mx0 = fmaxf(mx0, __shfl_xor_sync(0xffffffffu, mx0, 2));
        mx1 = fmaxf(mx1, __shfl_xor_sync(0xffffffffu, mx1, 1));
        mx1 = fmaxf(mx1, __shfl_xor_sync(0xffffffffu, mx1, 2));
        const float mn0 = fmaxf(m0, mx0);
        const float mn1 = fmaxf(m1, mx1);
        const float cr0 = __expf(m0 - mn0);
        const float cr1 = __expf(m1 - mn1);

        float s0 = 0.0f, s1 = 0.0f;
        #pragma unroll
        for (int n = 0; n < 8; n++) {
            float p0 = __expf(sacc[n][0] - mn0);
            float p1 = __expf(sacc[n][1] - mn0);
            float p2 = __expf(sacc[n][2] - mn1);
            float p3 = __expf(sacc[n][3] - mn1);
            s0 += p0 + p1;
            s1 += p2 + p3;
            *(float2*)&Ps[g * PS_STRIDE + n * 8 + 2 * qd]       = make_float2(t32(p0), t32(p1));
            *(float2*)&Ps[(g + 8) * PS_STRIDE + n * 8 + 2 * qd] = make_float2(t32(p2), t32(p3));
        }
        s0 += __shfl_xor_sync(0xffffffffu, s0, 1);
        s0 += __shfl_xor_sync(0xffffffffu, s0, 2);
        s1 += __shfl_xor_sync(0xffffffffu, s1, 1);
        s1 += __shfl_xor_sync(0xffffffffu, s1, 2);
        l0 = l0 * cr0 + s0;
        l1 = l1 * cr1 + s1;
        m0 = mn0;
        m1 = mn1;

        #pragma unroll
        for (int n = 0; n < 8; n++) {
            oacc[n][0] *= cr0; oacc[n][1] *= cr0;
            oacc[n][2] *= cr1; oacc[n][3] *= cr1;
        }
        __syncwarp();

        // ---- O += P * V
        #pragma unroll
        for (int k = 0; k < 8; k++) {
            uint32_t pa0 = __float_as_uint(Ps[g * PS_STRIDE + k * 8 + qd]);
            uint32_t pa1 = __float_as_uint(Ps[(g + 8) * PS_STRIDE + k * 8 + qd]);
            uint32_t pa2 = __float_as_uint(Ps[g * PS_STRIDE + k * 8 + qd + 4]);
            uint32_t pa3 = __float_as_uint(Ps[(g + 8) * PS_STRIDE + k * 8 + qd + 4]);
            #pragma unroll
            for (int n = 0; n < 8; n++) {
                uint32_t b0 = __float_as_uint(Vs[(k * 8 + qd) * VS_STRIDE + n * 8 + g]);
                uint32_t b1 = __float_as_uint(Vs[(k * 8 + qd + 4) * VS_STRIDE + n * 8 + g]);
                mma8(oacc[n][0], oacc[n][1], oacc[n][2], oacc[n][3],
                     pa0, pa1, pa2, pa3, b0, b1);
            }
        }
        __syncthreads();   // buffer `cur` fully consumed before tile t+2 overwrites it
    }

    // ---- epilogue: normalize, tf32-round
    const float inv0 = 1.0f / l0;
    const float inv1 = 1.0f / l1;
    const long row0 = (long)(b * SEQ + q0 + w * 16 + g);
    const long row1 = row0 + 8;
    #pragma unroll
    for (int n = 0; n < 8; n++) {
        int c = h * DHEAD + n * 8 + 2 * qd;
        *(float2*)(Og + row0 * DMODEL + c) = make_float2(t32(oacc[n][0] * inv0), t32(oacc[n][1] * inv0));
        *(float2*)(Og + row1 * DMODEL + c) = make_float2(t32(oacc[n][2] * inv1), t32(oacc[n][3] * inv1));
    }
}

// ---------------------------------------------------------------------------
// Launch
// ---------------------------------------------------------------------------
extern "C" void kernel_launch(void* const* d_in, const int* in_sizes, int n_in,
                              void* d_out, int out_size)
{
    const float* x  = (const float*)d_in[0];
    const float* wq = (const float*)d_in[1];
    const float* wk = (const float*)d_in[2];
    const float* wv = (const float*)d_in[3];
    const float* wo = (const float*)d_in[4];
    float* out = (float*)d_out;

    float *qb, *kb, *vb, *ab, *xr, *wr;
    cudaGetSymbolAddress((void**)&qb, g_q);
    cudaGetSymbolAddress((void**)&kb, g_k);
    cudaGetSymbolAddress((void**)&vb, g_v);
    cudaGetSymbolAddress((void**)&ab, g_att);
    cudaGetSymbolAddress((void**)&xr, g_xr);
    cudaGetSymbolAddress((void**)&wr, g_wr);

    float* wqr = wr;
    float* wkr = wr + (size_t)DMODEL * DMODEL;
    float* wvr = wr + 2 * (size_t)DMODEL * DMODEL;
    float* wor = wr + 3 * (size_t)DMODEL * DMODEL;

    const int NX4 = MROWS * DMODEL / 4;
    const int NW4 = DMODEL * DMODEL / 4;
    round_tf32<<<(NX4 + 255) / 256, 256>>>(x,  xr,  NX4);
    round_tf32<<<(NW4 + 255) / 256, 256>>>(wq, wqr, NW4);
    round_tf32<<<(NW4 + 255) / 256, 256>>>(wk, wkr, NW4);
    round_tf32<<<(NW4 + 255) / 256, 256>>>(wv, wvr, NW4);
    round_tf32<<<(NW4 + 255) / 256, 256>>>(wo, wor, NW4);

    cudaFuncSetAttribute((const void*)gemm_cp<3, true>, cudaFuncAttributeMaxDynamicSharedMemorySize, GEMM_SMEM);
    cudaFuncSetAttribute((const void*)gemm_cp<1, false>, cudaFuncAttributeMaxDynamicSharedMemorySize, GEMM_SMEM);

    dim3 gq(DMODEL / 128, MROWS / 128, 3);   // (8, 64, 3)
    gemm_cp<3, true><<<gq, 256, GEMM_SMEM>>>(xr, wqr, wkr, wvr, qb, kb, vb, MROWS, DMODEL, DMODEL);

    cudaFuncSetAttribute(flash5, cudaFuncAttributeMaxDynamicSharedMemorySize, FL_SMEM);
    dim3 fg(SEQ / 64, NHEAD, BATCH);         // (32, 16, 4)
    flash5<<<fg, 128, FL_SMEM>>>(qb, kb, vb, ab);

    dim3 go(DMODEL / 128, MROWS / 128, 1);   // (8, 64)
    gemm_cp<1, false><<<go, 256, GEMM_SMEM>>>(ab, wor, nullptr, nullptr, out, nullptr, nullptr,
                                              MROWS, DMODEL, DMODEL);
}

// round 9
// speedup vs baseline: 7.1383x; 1.6477x over previous
#include <cuda_runtime.h>
#include <cuda_fp16.h>
#include <cstddef>
#include <cstdint>

// Problem constants
static constexpr int BATCH  = 4;
static constexpr int SEQ    = 2048;
static constexpr int DMODEL = 1024;
static constexpr int NHEAD  = 16;
static constexpr int DHEAD  = 64;
static constexpr int MROWS  = BATCH * SEQ;   // 8192

// Scratch (device globals — no allocations allowed). All activations fp16.
__device__ __half g_q[MROWS * DMODEL];
__device__ __half g_k[MROWS * DMODEL];
__device__ __half g_v[MROWS * DMODEL];
__device__ __half g_vt[DMODEL * MROWS];         // V transposed [d_model][rows]
__device__ __half g_att[MROWS * DMODEL];
__device__ __half g_xh[MROWS * DMODEL];         // fp16 x
__device__ __half g_wh[4 * DMODEL * DMODEL];    // fp16 W^T (Q,K,V,O), [N][K]

// ---------------- helpers ----------------
__device__ __forceinline__ uint32_t smem_u32(const void* p) {
    return (uint32_t)__cvta_generic_to_shared(p);
}
__device__ __forceinline__ void cp16s(uint32_t smem_dst, const void* gsrc) {
    asm volatile("cp.async.cg.shared.global [%0], [%1], 16;\n" :: "r"(smem_dst), "l"(gsrc));
}
__device__ __forceinline__ void cp16(void* smem_dst, const void* gsrc) {
    cp16s(smem_u32(smem_dst), gsrc);
}
__device__ __forceinline__ void cp_commit() { asm volatile("cp.async.commit_group;\n"); }
template <int N>
__device__ __forceinline__ void cp_wait() { asm volatile("cp.async.wait_group %0;\n" :: "n"(N)); }

// mma.m16n8k16 fp16 in, fp32 accumulate. row.col.
__device__ __forceinline__ void mma16(float& c0, float& c1, float& c2, float& c3,
                                      uint32_t a0, uint32_t a1, uint32_t a2, uint32_t a3,
                                      uint32_t b0, uint32_t b1)
{
    asm volatile(
        "mma.sync.aligned.m16n8k16.row.col.f32.f16.f16.f32 "
        "{%0,%1,%2,%3}, {%4,%5,%6,%7}, {%8,%9}, {%0,%1,%2,%3};\n"
        : "+f"(c0), "+f"(c1), "+f"(c2), "+f"(c3)
        : "r"(a0), "r"(a1), "r"(a2), "r"(a3), "r"(b0), "r"(b1));
}

__device__ __forceinline__ uint32_t packh2(float a, float b) {
    __half2 h = __floats2half2_rn(a, b);
    return *(uint32_t*)&h;
}

// ---------------------------------------------------------------------------
// fp32 -> fp16 elementwise
// ---------------------------------------------------------------------------
__global__ __launch_bounds__(256) void f32_to_f16(const float* __restrict__ in,
                                                  __half* __restrict__ out, int n4)
{
    int i = blockIdx.x * 256 + threadIdx.x;
    if (i < n4) {
        float4 v = ((const float4*)in)[i];
        uint2 u;
        u.x = packh2(v.x, v.y);
        u.y = packh2(v.z, v.w);
        ((uint2*)out)[i] = u;
    }
}

// ---------------------------------------------------------------------------
// Transpose + fp16-round a 1024x1024 fp32 weight: out[n][k] = h(in[k][n]).
// ---------------------------------------------------------------------------
__global__ __launch_bounds__(256) void transpose_w(const float* __restrict__ in,
                                                   __half* __restrict__ out)
{
    __shared__ float t[32][33];
    const int bx = blockIdx.x * 32, by = blockIdx.y * 32;
    const int tx = threadIdx.x & 31, ty = threadIdx.x >> 5;
    #pragma unroll
    for (int j = 0; j < 32; j += 8)
        t[ty + j][tx] = in[(long)(by + ty + j) * DMODEL + bx + tx];
    __syncthreads();
    #pragma unroll
    for (int j = 0; j < 32; j += 8)
        out[(long)(bx + ty + j) * DMODEL + by + tx] = __float2half_rn(t[tx][ty + j]);
}

// ---------------------------------------------------------------------------
// Transpose fp16 V: [MROWS][DMODEL] -> [DMODEL][MROWS], 64x64 tiles.
// ---------------------------------------------------------------------------
__global__ __launch_bounds__(256) void transpose_v(const __half* __restrict__ in,
                                                   __half* __restrict__ out)
{
    __shared__ __half t[64][72];
    const int bx = blockIdx.x * 64;   // DMODEL base
    const int by = blockIdx.y * 64;   // MROWS base
    const int tid = threadIdx.x;
    #pragma unroll
    for (int i = 0; i < 2; i++) {
        int idx = tid + i * 256;
        int row = idx >> 3, c8 = (idx & 7) * 8;
        *(uint4*)&t[row][c8] = *(const uint4*)(in + (long)(by + row) * DMODEL + bx + c8);
    }
    __syncthreads();
    #pragma unroll
    for (int i = 0; i < 2; i++) {
        int idx = tid + i * 256;
        int oc = idx >> 3, r8 = (idx & 7) * 8;
        __half tmp[8];
        #pragma unroll
        for (int j = 0; j < 8; j++) tmp[j] = t[r8 + j][oc];
        *(uint4*)(out + (long)(bx + oc) * MROWS + by + r8) = *(uint4*)tmp;
    }
}

// ---------------------------------------------------------------------------
// fp16 GEMM: C[M,N] = A[M,K] * Bt[N,K]^T, A/Bt fp16 row-major, fp32 accum.
// 128x128x32 tile, 256 thr = 8 warps, warp 64x32 (4x4 m16n8k16 tiles).
// Smem: half, row stride 40 (conflict-free frag loads). cp.async double-buf.
// OUT_HALF: write fp16 (QKV); else fp32 (final output).
// ---------------------------------------------------------------------------
static constexpr int HS = 40;                       // halves per smem row
static constexpr int HBUF = 128 * HS;               // halves per buffer
static constexpr int GEMM_SMEM = 4 * HBUF * 2;      // 2 bufs x (A+B) = 40960 B

template <int NMAT, bool OUT_HALF>
__global__ __launch_bounds__(256, 2) void gemm_h(
    const __half* __restrict__ A,
    const __half* __restrict__ B0, const __half* __restrict__ B1, const __half* __restrict__ B2,
    void* __restrict__ C0, void* __restrict__ C1, void* __restrict__ C2)
{
    extern __shared__ __half hsm[];
    __half* As = hsm;                 // [2][128][40]
    __half* Bs = hsm + 2 * HBUF;      // [2][128][40]

    const __half* Bt = B0;
    void* C = C0;
    if (NMAT > 1) {
        if (blockIdx.z == 1) { Bt = B1; C = C1; }
        else if (blockIdx.z == 2) { Bt = B2; C = C2; }
    }

    const int tid = threadIdx.x;
    const int wid = tid >> 5;
    const int l   = tid & 31;
    const int g   = l >> 2;
    const int qd  = l & 3;
    const int wm  = (wid & 1) * 64;
    const int wn  = (wid >> 1) * 32;
    const long bm0 = (long)blockIdx.y * 128;
    const long bn0 = (long)blockIdx.x * 128;

    float acc[4][4][4];
    #pragma unroll
    for (int i = 0; i < 4; i++)
        #pragma unroll
        for (int j = 0; j < 4; j++)
            #pragma unroll
            for (int e = 0; e < 4; e++) acc[i][j][e] = 0.0f;

    const uint32_t asb = smem_u32(As);
    const uint32_t bsb = smem_u32(Bs);

    // chunk loader: A/B each 128 rows x 32 halves (64B) -> 4 cp16 per row
    auto load_chunk = [&](int k0, int buf) {
        const uint32_t ab = asb + buf * HBUF * 2;
        const uint32_t bb = bsb + buf * HBUF * 2;
        #pragma unroll
        for (int i = 0; i < 2; i++) {
            int idx = tid + i * 256;
            int row = idx >> 2, ci = idx & 3;
            cp16s(ab + row * (HS * 2) + ci * 16, A  + (bm0 + row) * DMODEL + k0 + ci * 8);
            cp16s(bb + row * (HS * 2) + ci * 16, Bt + (bn0 + row) * DMODEL + k0 + ci * 8);
        }
        cp_commit();
    };

    load_chunk(0, 0);
    cp_wait<0>();
    __syncthreads();

    int cur = 0;
    for (int k0 = 32; k0 <= DMODEL; k0 += 32) {
        const bool more = (k0 < DMODEL);
        if (more) load_chunk(k0, cur ^ 1);

        const __half* Ac = As + cur * HBUF;
        const __half* Bc = Bs + cur * HBUF;
        #pragma unroll
        for (int ks = 0; ks < 2; ks++) {
            const int kb = ks * 16 + 2 * qd;
            uint32_t af[4][4];
            #pragma unroll
            for (int tm = 0; tm < 4; tm++) {
                const int r0 = (wm + tm * 16 + g) * HS + kb;
                const int r1 = r0 + 8 * HS;
                af[tm][0] = *(const uint32_t*)(Ac + r0);
                af[tm][1] = *(const uint32_t*)(Ac + r1);
                af[tm][2] = *(const uint32_t*)(Ac + r0 + 8);
                af[tm][3] = *(const uint32_t*)(Ac + r1 + 8);
            }
            uint32_t bf[4][2];
            #pragma unroll
            for (int tn = 0; tn < 4; tn++) {
                const int rb = (wn + tn * 8 + g) * HS + kb;
                bf[tn][0] = *(const uint32_t*)(Bc + rb);
                bf[tn][1] = *(const uint32_t*)(Bc + rb + 8);
            }
            #pragma unroll
            for (int tm = 0; tm < 4; tm++)
                #pragma unroll
                for (int tn = 0; tn < 4; tn++)
                    mma16(acc[tm][tn][0], acc[tm][tn][1], acc[tm][tn][2], acc[tm][tn][3],
                          af[tm][0], af[tm][1], af[tm][2], af[tm][3],
                          bf[tn][0], bf[tn][1]);
        }

        if (more) {
            cp_wait<0>();
            __syncthreads();
            cur ^= 1;
        }
    }

    // epilogue
    #pragma unroll
    for (int tm = 0; tm < 4; tm++) {
        const long row0 = bm0 + wm + tm * 16 + g;
        const long row1 = row0 + 8;
        #pragma unroll
        for (int tn = 0; tn < 4; tn++) {
            const long col = bn0 + wn + tn * 8 + 2 * qd;
            if (OUT_HALF) {
                __half* Ch = (__half*)C;
                *(uint32_t*)(Ch + row0 * DMODEL + col) = packh2(acc[tm][tn][0], acc[tm][tn][1]);
                *(uint32_t*)(Ch + row1 * DMODEL + col) = packh2(acc[tm][tn][2], acc[tm][tn][3]);
            } else {
                float* Cf = (float*)C;
                *(float2*)(Cf + row0 * DMODEL + col) = make_float2(acc[tm][tn][0], acc[tm][tn][1]);
                *(float2*)(Cf + row1 * DMODEL + col) = make_float2(acc[tm][tn][2], acc[tm][tn][3]);
            }
        }
    }
}

// ---------------------------------------------------------------------------
// Flash attention fp16 (causal): FA2-style, m16n8k16, P entirely in registers
// (S C-fragment layout == P A-fragment layout). K: [key][d] smem; V: [d][key]
// smem from pre-transposed g_vt. Double-buffered cp.async. fp32 softmax/accum.
// ---------------------------------------------------------------------------
static constexpr int FS = 72;                         // halves per smem row
static constexpr int FBUF = 64 * FS;                  // halves per tile buffer
static constexpr int FL_SMEM = 4 * FBUF * 2;          // 36864 B

__global__ __launch_bounds__(128, 3) void flash6(
    const __half* __restrict__ Qg, const __half* __restrict__ Kg,
    const __half* __restrict__ Vt, __half* __restrict__ Og)
{
    extern __shared__ __half fsm[];
    __half* Ksb = fsm;                // [2][64][72]
    __half* Vsb = fsm + 2 * FBUF;     // [2][64][72]

    const int tid = threadIdx.x;
    const int w   = tid >> 5;
    const int l   = tid & 31;
    const int g   = l >> 2;
    const int qd  = l & 3;
    const int b = blockIdx.z, h = blockIdx.y;
    const int q0 = blockIdx.x * 64;

    // ---- Stage Q (x0.125, exact in fp16) into Ksb[0], pull frags to regs
    {
        const __half2 hs = __float2half2_rn(0.125f);
        #pragma unroll
        for (int r = 0; r < 4; r++) {
            int idx = tid + r * 128;
            int row = idx >> 3, c8 = (idx & 7) * 8;
            uint4 v = *(const uint4*)(Qg + (long)(b * SEQ + q0 + row) * DMODEL + h * DHEAD + c8);
            __half2* d = (__half2*)&Ksb[row * FS + c8];
            d[0] = __hmul2(*(__half2*)&v.x, hs);
            d[1] = __hmul2(*(__half2*)&v.y, hs);
            d[2] = __hmul2(*(__half2*)&v.z, hs);
            d[3] = __hmul2(*(__half2*)&v.w, hs);
        }
    }
    __syncthreads();

    uint32_t qa[4][4];   // 4 k-steps over d=64
    {
        const int r0 = (w * 16 + g) * FS;
        const int r1 = (w * 16 + g + 8) * FS;
        #pragma unroll
        for (int ks = 0; ks < 4; ks++) {
            const int kb = ks * 16 + 2 * qd;
            qa[ks][0] = *(const uint32_t*)(Ksb + r0 + kb);
            qa[ks][1] = *(const uint32_t*)(Ksb + r1 + kb);
            qa[ks][2] = *(const uint32_t*)(Ksb + r0 + kb + 8);
            qa[ks][3] = *(const uint32_t*)(Ksb + r1 + kb + 8);
        }
    }
    __syncthreads();   // Q-frag reads done before cp.async overwrites buf 0

    float oacc[8][4];
    #pragma unroll
    for (int n = 0; n < 8; n++)
        #pragma unroll
        for (int e = 0; e < 4; e++) oacc[n][e] = 0.0f;
    float m0 = -1e30f, m1 = -1e30f, l0 = 0.0f, l1 = 0.0f;

    const int ntiles = blockIdx.x + 1;
    const long kq_base = (long)b * SEQ * DMODEL + h * DHEAD;       // K: [row][d]
    const long vt_base = (long)h * DHEAD * MROWS + (long)b * SEQ;  // Vt: [d][row]

    // loaders: K tile [64 key][64 d], V tile [64 d][64 key]; 8 cp16/thr total
    auto load_tile = [&](int t, int buf) {
        __half* Kb = Ksb + buf * FBUF;
        __half* Vb = Vsb + buf * FBUF;
        const long koff = kq_base + (long)t * 64 * DMODEL;
        const long voff = vt_base + (long)t * 64;
        #pragma unroll
        for (int r = 0; r < 4; r++) {
            int idx = tid + r * 128;
            int row = idx >> 3, c8 = (idx & 7) * 8;
            cp16(&Kb[row * FS + c8], Kg + koff + (long)row * DMODEL + c8);
            cp16(&Vb[row * FS + c8], Vt + voff + (long)row * MROWS + c8);
        }
        cp_commit();
    };

    load_tile(0, 0);

    for (int t = 0; t < ntiles; t++) {
        const int cur = t & 1;
        if (t + 1 < ntiles) {
            load_tile(t + 1, cur ^ 1);
            cp_wait<1>();
        } else {
            cp_wait<0>();
        }
        __syncthreads();

        const __half* Ks = Ksb + cur * FBUF;
        const __half* Vs = Vsb + cur * FBUF;

        // ---- S = Q * K^T (8 n-tiles x 4 k-steps)
        float sacc[8][4];
        #pragma unroll
        for (int n = 0; n < 8; n++) {
            sacc[n][0] = sacc[n][1] = sacc[n][2] = sacc[n][3] = 0.0f;
            const int rb = (n * 8 + g) * FS;
            #pragma unroll
            for (int ks = 0; ks < 4; ks++) {
                const int kb = ks * 16 + 2 * qd;
                uint32_t b0 = *(const uint32_t*)(Ks + rb + kb);
                uint32_t b1 = *(const uint32_t*)(Ks + rb + kb + 8);
                mma16(sacc[n][0], sacc[n][1], sacc[n][2], sacc[n][3],
                      qa[ks][0], qa[ks][1], qa[ks][2], qa[ks][3], b0, b1);
            }
        }

        // ---- causal mask (diagonal tile only)
        if (t == ntiles - 1) {
            const int r0 = w * 16 + g, r1 = r0 + 8;
            #pragma unroll
            for (int n = 0; n < 8; n++) {
                int c0 = n * 8 + 2 * qd, c1 = c0 + 1;
                if (c0 > r0) sacc[n][0] = -1e30f;
                if (c1 > r0) sacc[n][1] = -1e30f;
                if (c0 > r1) sacc[n][2] = -1e30f;
                if (c1 > r1) sacc[n][3] = -1e30f;
            }
        }

        // ---- online softmax in registers
        float mx0 = -1e30f, mx1 = -1e30f;
        #pragma unroll
        for (int n = 0; n < 8; n++) {
            mx0 = fmaxf(mx0, fmaxf(sacc[n][0], sacc[n][1]));
            mx1 = fmaxf(mx1, fmaxf(sacc[n][2], sacc[n][3]));
        }
        mx0 = fmaxf(mx0, __shfl_xor_sync(0xffffffffu, mx0, 1));
        mx0 = fmaxf(mx0, __shfl_xor_sync(0xffffffffu, mx0, 2));
        mx1 = fmaxf(mx1, __shfl_xor_sync(0xffffffffu, mx1, 1));
        mx1 = fmaxf(mx1, __shfl_xor_sync(0xffffffffu, mx1, 2));
        const float mn0 = fmaxf(m0, mx0);
        const float mn1 = fmaxf(m1, mx1);
        const float cr0 = __expf(m0 - mn0);
        const float cr1 = __expf(m1 - mn1);

        uint32_t pp0[8], pp1[8];   // P packed: rows g / g+8
        float s0 = 0.0f, s1 = 0.0f;
        #pragma unroll
        for (int n = 0; n < 8; n++) {
            float p0 = __expf(sacc[n][0] - mn0);
            float p1 = __expf(sacc[n][1] - mn0);
            float p2 = __expf(sacc[n][2] - mn1);
            float p3 = __expf(sacc[n][3] - mn1);
            s0 += p0 + p1;
            s1 += p2 + p3;
            pp0[n] = packh2(p0, p1);
            pp1[n] = packh2(p2, p3);
        }
        s0 += __shfl_xor_sync(0xffffffffu, s0, 1);
        s0 += __shfl_xor_sync(0xffffffffu, s0, 2);
        s1 += __shfl_xor_sync(0xffffffffu, s1, 1);
        s1 += __shfl_xor_sync(0xffffffffu, s1, 2);
        l0 = l0 * cr0 + s0;
        l1 = l1 * cr1 + s1;
        m0 = mn0;
        m1 = mn1;

        #pragma unroll
        for (int n = 0; n < 8; n++) {
            oacc[n][0] *= cr0; oacc[n][1] *= cr0;
            oacc[n][2] *= cr1; oacc[n][3] *= cr1;
        }

        // ---- O += P * V  (P from registers; V^T from smem)
        #pragma unroll
        for (int ks = 0; ks < 4; ks++) {
            const uint32_t a0 = pp0[2 * ks],     a1 = pp1[2 * ks];
            const uint32_t a2 = pp0[2 * ks + 1], a3 = pp1[2 * ks + 1];
            const int kb = ks * 16 + 2 * qd;
            #pragma unroll
            for (int n = 0; n < 8; n++) {
                const int rb = (n * 8 + g) * FS + kb;
                uint32_t b0 = *(const uint32_t*)(Vs + rb);
                uint32_t b1 = *(const uint32_t*)(Vs + rb + 8);
                mma16(oacc[n][0], oacc[n][1], oacc[n][2], oacc[n][3],
                      a0, a1, a2, a3, b0, b1);
            }
        }
        __syncthreads();   // buffer `cur` consumed before tile t+2 overwrites
    }

    // ---- epilogue: normalize, write fp16
    const float inv0 = 1.0f / l0;
    const float inv1 = 1.0f / l1;
    const long row0 = (long)(b * SEQ + q0 + w * 16 + g);
    const long row1 = row0 + 8;
    #pragma unroll
    for (int n = 0; n < 8; n++) {
        int c = h * DHEAD + n * 8 + 2 * qd;
        *(uint32_t*)(Og + row0 * DMODEL + c) = packh2(oacc[n][0] * inv0, oacc[n][1] * inv0);
        *(uint32_t*)(Og + row1 * DMODEL + c) = packh2(oacc[n][2] * inv1, oacc[n][3] * inv1);
    }
}

// ---------------------------------------------------------------------------
// Launch
// ---------------------------------------------------------------------------
extern "C" void kernel_launch(void* const* d_in, const int* in_sizes, int n_in,
                              void* d_out, int out_size)
{
    const float* x  = (const float*)d_in[0];
    const float* wq = (const float*)d_in[1];
    const float* wk = (const float*)d_in[2];
    const float* wv = (const float*)d_in[3];
    const float* wo = (const float*)d_in[4];
    float* out = (float*)d_out;

    __half *qb, *kb, *vb, *vtb, *ab, *xh, *wh;
    cudaGetSymbolAddress((void**)&qb,  g_q);
    cudaGetSymbolAddress((void**)&kb,  g_k);
    cudaGetSymbolAddress((void**)&vb,  g_v);
    cudaGetSymbolAddress((void**)&vtb, g_vt);
    cudaGetSymbolAddress((void**)&ab,  g_att);
    cudaGetSymbolAddress((void**)&xh,  g_xh);
    cudaGetSymbolAddress((void**)&wh,  g_wh);

    __half* wqt = wh;
    __half* wkt = wh + (size_t)DMODEL * DMODEL;
    __half* wvt = wh + 2 * (size_t)DMODEL * DMODEL;
    __half* wot = wh + 3 * (size_t)DMODEL * DMODEL;

    // Pre-passes: x -> fp16; W -> transposed fp16 [N][K]
    const int NX4 = MROWS * DMODEL / 4;
    f32_to_f16<<<(NX4 + 255) / 256, 256>>>(x, xh, NX4);
    dim3 tg(DMODEL / 32, DMODEL / 32);
    transpose_w<<<tg, 256>>>(wq, wqt);
    transpose_w<<<tg, 256>>>(wk, wkt);
    transpose_w<<<tg, 256>>>(wv, wvt);
    transpose_w<<<tg, 256>>>(wo, wot);

    cudaFuncSetAttribute((const void*)gemm_h<3, true>,  cudaFuncAttributeMaxDynamicSharedMemorySize, GEMM_SMEM);
    cudaFuncSetAttribute((const void*)gemm_h<1, false>, cudaFuncAttributeMaxDynamicSharedMemorySize, GEMM_SMEM);

    // Fused QKV projection (fp16 out)
    dim3 gq(DMODEL / 128, MROWS / 128, 3);   // (8, 64, 3)
    gemm_h<3, true><<<gq, 256, GEMM_SMEM>>>(xh, wqt, wkt, wvt, qb, kb, vb);

    // V transpose for PV B-operand
    dim3 vg(DMODEL / 64, MROWS / 64);        // (16, 128)
    transpose_v<<<vg, 256>>>(vb, vtb);

    cudaFuncSetAttribute(flash6, cudaFuncAttributeMaxDynamicSharedMemorySize, FL_SMEM);
    dim3 fg(SEQ / 64, NHEAD, BATCH);         // (32, 16, 4)
    flash6<<<fg, 128, FL_SMEM>>>(qb, kb, vtb, ab);

    // Output projection (fp32 out)
    dim3 go(DMODEL / 128, MROWS / 128, 1);   // (8, 64)
    gemm_h<1, false><<<go, 256, GEMM_SMEM>>>(ab, wot, nullptr, nullptr, out, nullptr, nullptr);
}

// round 10
// speedup vs baseline: 7.9774x; 1.1176x over previous
#include <cuda_runtime.h>
#include <cuda_fp16.h>
#include <cstddef>
#include <cstdint>

// Problem constants
static constexpr int BATCH  = 4;
static constexpr int SEQ    = 2048;
static constexpr int DMODEL = 1024;
static constexpr int NHEAD  = 16;
static constexpr int DHEAD  = 64;
static constexpr int MROWS  = BATCH * SEQ;   // 8192

// Scratch (device globals). All activations fp16.
__device__ __half g_q[MROWS * DMODEL];
__device__ __half g_k[MROWS * DMODEL];
__device__ __half g_v[MROWS * DMODEL];
__device__ __half g_vt[DMODEL * MROWS];         // V transposed [d_model][rows]
__device__ __half g_att[MROWS * DMODEL];
__device__ __half g_xh[MROWS * DMODEL];         // fp16 x
__device__ __half g_wh[4 * DMODEL * DMODEL];    // fp16 W^T (Q,K,V,O), [N][K]

// ---------------- helpers ----------------
__device__ __forceinline__ uint32_t smem_u32(const void* p) {
    return (uint32_t)__cvta_generic_to_shared(p);
}
__device__ __forceinline__ void cp16s(uint32_t smem_dst, const void* gsrc) {
    asm volatile("cp.async.cg.shared.global [%0], [%1], 16;\n" :: "r"(smem_dst), "l"(gsrc));
}
__device__ __forceinline__ void cp16(void* smem_dst, const void* gsrc) {
    cp16s(smem_u32(smem_dst), gsrc);
}
__device__ __forceinline__ void cp_commit() { asm volatile("cp.async.commit_group;\n"); }
template <int N>
__device__ __forceinline__ void cp_wait() { asm volatile("cp.async.wait_group %0;\n" :: "n"(N)); }

// mma.m16n8k16 fp16 in, fp32 accumulate. row.col.
__device__ __forceinline__ void mma16(float& c0, float& c1, float& c2, float& c3,
                                      uint32_t a0, uint32_t a1, uint32_t a2, uint32_t a3,
                                      uint32_t b0, uint32_t b1)
{
    asm volatile(
        "mma.sync.aligned.m16n8k16.row.col.f32.f16.f16.f32 "
        "{%0,%1,%2,%3}, {%4,%5,%6,%7}, {%8,%9}, {%0,%1,%2,%3};\n"
        : "+f"(c0), "+f"(c1), "+f"(c2), "+f"(c3)
        : "r"(a0), "r"(a1), "r"(a2), "r"(a3), "r"(b0), "r"(b1));
}

// ldmatrix x4 (non-transposed)
__device__ __forceinline__ void ldsm4(uint32_t& r0, uint32_t& r1, uint32_t& r2, uint32_t& r3,
                                      uint32_t saddr)
{
    asm volatile("ldmatrix.sync.aligned.m8n8.x4.shared.b16 {%0,%1,%2,%3}, [%4];"
                 : "=r"(r0), "=r"(r1), "=r"(r2), "=r"(r3) : "r"(saddr));
}

__device__ __forceinline__ uint32_t packh2(float a, float b) {
    __half2 h = __floats2half2_rn(a, b);
    return *(uint32_t*)&h;
}

// ---------------------------------------------------------------------------
// fp32 -> fp16 elementwise
// ---------------------------------------------------------------------------
__global__ __launch_bounds__(256) void f32_to_f16(const float* __restrict__ in,
                                                  __half* __restrict__ out, int n4)
{
    int i = blockIdx.x * 256 + threadIdx.x;
    if (i < n4) {
        float4 v = ((const float4*)in)[i];
        uint2 u;
        u.x = packh2(v.x, v.y);
        u.y = packh2(v.z, v.w);
        ((uint2*)out)[i] = u;
    }
}

// ---------------------------------------------------------------------------
// Fused: transpose + fp16-round all four 1024x1024 weights (grid.z selects).
// ---------------------------------------------------------------------------
__global__ __launch_bounds__(256) void transpose_w4(
    const float* __restrict__ w0, const float* __restrict__ w1,
    const float* __restrict__ w2, const float* __restrict__ w3,
    __half* __restrict__ o0, __half* __restrict__ o1,
    __half* __restrict__ o2, __half* __restrict__ o3)
{
    const float* in = w0; __half* out = o0;
    if (blockIdx.z == 1) { in = w1; out = o1; }
    else if (blockIdx.z == 2) { in = w2; out = o2; }
    else if (blockIdx.z == 3) { in = w3; out = o3; }

    __shared__ float t[32][33];
    const int bx = blockIdx.x * 32, by = blockIdx.y * 32;
    const int tx = threadIdx.x & 31, ty = threadIdx.x >> 5;
    #pragma unroll
    for (int j = 0; j < 32; j += 8)
        t[ty + j][tx] = in[(long)(by + ty + j) * DMODEL + bx + tx];
    __syncthreads();
    #pragma unroll
    for (int j = 0; j < 32; j += 8)
        out[(long)(bx + ty + j) * DMODEL + by + tx] = __float2half_rn(t[tx][ty + j]);
}

// ---------------------------------------------------------------------------
// Transpose fp16 V: [MROWS][DMODEL] -> [DMODEL][MROWS], 64x64 tiles.
// ---------------------------------------------------------------------------
__global__ __launch_bounds__(256) void transpose_v(const __half* __restrict__ in,
                                                   __half* __restrict__ out)
{
    __shared__ __half t[64][72];
    const int bx = blockIdx.x * 64;   // DMODEL base
    const int by = blockIdx.y * 64;   // MROWS base
    const int tid = threadIdx.x;
    #pragma unroll
    for (int i = 0; i < 2; i++) {
        int idx = tid + i * 256;
        int row = idx >> 3, c8 = (idx & 7) * 8;
        *(uint4*)&t[row][c8] = *(const uint4*)(in + (long)(by + row) * DMODEL + bx + c8);
    }
    __syncthreads();
    #pragma unroll
    for (int i = 0; i < 2; i++) {
        int idx = tid + i * 256;
        int oc = idx >> 3, r8 = (idx & 7) * 8;
        __half tmp[8];
        #pragma unroll
        for (int j = 0; j < 8; j++) tmp[j] = t[r8 + j][oc];
        *(uint4*)(out + (long)(bx + oc) * MROWS + by + r8) = *(uint4*)tmp;
    }
}

// ---------------------------------------------------------------------------
// fp16 GEMM with ldmatrix fragment loads. C = A[M,K] * Bt[N,K]^T, fp32 accum.
// 128x128x32 tile, 256 thr = 8 warps, warp 64x32. Stride 40 halves.
// ---------------------------------------------------------------------------
static constexpr int HS = 40;                       // halves per smem row
static constexpr int HBUF = 128 * HS;               // halves per buffer
static constexpr int GEMM_SMEM = 4 * HBUF * 2;      // 40960 B

template <int NMAT, bool OUT_HALF>
__global__ __launch_bounds__(256, 2) void gemm_h(
    const __half* __restrict__ A,
    const __half* __restrict__ B0, const __half* __restrict__ B1, const __half* __restrict__ B2,
    void* __restrict__ C0, void* __restrict__ C1, void* __restrict__ C2)
{
    extern __shared__ __half hsm[];
    __half* As = hsm;                 // [2][128][40]
    __half* Bs = hsm + 2 * HBUF;      // [2][128][40]

    const __half* Bt = B0;
    void* C = C0;
    if (NMAT > 1) {
        if (blockIdx.z == 1) { Bt = B1; C = C1; }
        else if (blockIdx.z == 2) { Bt = B2; C = C2; }
    }

    const int tid = threadIdx.x;
    const int wid = tid >> 5;
    const int l   = tid & 31;
    const int g   = l >> 2;
    const int qd  = l & 3;
    const int wm  = (wid & 1) * 64;
    const int wn  = (wid >> 1) * 32;
    const long bm0 = (long)blockIdx.y * 128;
    const long bn0 = (long)blockIdx.x * 128;

    // ldmatrix per-lane offsets (in halves)
    const int a_m = (l & 7) + ((l >> 3) & 1) * 8;   // m offset within 16-row tile
    const int a_k = (l >> 4) * 8;                   // k offset (which k-half)
    const int b_n = (l & 7) + (l >> 4) * 8;         // n offset within 16-row pair
    const int b_k = ((l >> 3) & 1) * 8;             // k offset

    float acc[4][4][4];
    #pragma unroll
    for (int i = 0; i < 4; i++)
        #pragma unroll
        for (int j = 0; j < 4; j++)
            #pragma unroll
            for (int e = 0; e < 4; e++) acc[i][j][e] = 0.0f;

    const uint32_t asb = smem_u32(As);
    const uint32_t bsb = smem_u32(Bs);

    auto load_chunk = [&](int k0, int buf) {
        const uint32_t ab = asb + buf * HBUF * 2;
        const uint32_t bb = bsb + buf * HBUF * 2;
        #pragma unroll
        for (int i = 0; i < 2; i++) {
            int idx = tid + i * 256;
            int row = idx >> 2, ci = idx & 3;
            cp16s(ab + row * (HS * 2) + ci * 16, A  + (bm0 + row) * DMODEL + k0 + ci * 8);
            cp16s(bb + row * (HS * 2) + ci * 16, Bt + (bn0 + row) * DMODEL + k0 + ci * 8);
        }
        cp_commit();
    };

    load_chunk(0, 0);
    cp_wait<0>();
    __syncthreads();

    int cur = 0;
    for (int k0 = 32; k0 <= DMODEL; k0 += 32) {
        const bool more = (k0 < DMODEL);
        if (more) load_chunk(k0, cur ^ 1);

        const uint32_t acb = asb + cur * HBUF * 2;
        const uint32_t bcb = bsb + cur * HBUF * 2;
        #pragma unroll
        for (int ks = 0; ks < 2; ks++) {
            const int kb0 = ks * 16;
            uint32_t af[4][4];
            #pragma unroll
            for (int tm = 0; tm < 4; tm++)
                ldsm4(af[tm][0], af[tm][1], af[tm][2], af[tm][3],
                      acb + ((wm + tm * 16 + a_m) * HS + kb0 + a_k) * 2);
            uint32_t bf[4][2];
            #pragma unroll
            for (int tp = 0; tp < 2; tp++)
                ldsm4(bf[2 * tp][0], bf[2 * tp][1], bf[2 * tp + 1][0], bf[2 * tp + 1][1],
                      bcb + ((wn + tp * 16 + b_n) * HS + kb0 + b_k) * 2);
            #pragma unroll
            for (int tm = 0; tm < 4; tm++)
                #pragma unroll
                for (int tn = 0; tn < 4; tn++)
                    mma16(acc[tm][tn][0], acc[tm][tn][1], acc[tm][tn][2], acc[tm][tn][3],
                          af[tm][0], af[tm][1], af[tm][2], af[tm][3],
                          bf[tn][0], bf[tn][1]);
        }

        if (more) {
            cp_wait<0>();
            __syncthreads();
            cur ^= 1;
        }
    }

    // epilogue
    #pragma unroll
    for (int tm = 0; tm < 4; tm++) {
        const long row0 = bm0 + wm + tm * 16 + g;
        const long row1 = row0 + 8;
        #pragma unroll
        for (int tn = 0; tn < 4; tn++) {
            const long col = bn0 + wn + tn * 8 + 2 * qd;
            if (OUT_HALF) {
                __half* Ch = (__half*)C;
                *(uint32_t*)(Ch + row0 * DMODEL + col) = packh2(acc[tm][tn][0], acc[tm][tn][1]);
                *(uint32_t*)(Ch + row1 * DMODEL + col) = packh2(acc[tm][tn][2], acc[tm][tn][3]);
            } else {
                float* Cf = (float*)C;
                *(float2*)(Cf + row0 * DMODEL + col) = make_float2(acc[tm][tn][0], acc[tm][tn][1]);
                *(float2*)(Cf + row1 * DMODEL + col) = make_float2(acc[tm][tn][2], acc[tm][tn][3]);
            }
        }
    }
}

// ---------------------------------------------------------------------------
// Flash attention fp16 (causal), ldmatrix fragment loads. P in registers.
// K: [key][d] smem; V: [d][key] smem (from g_vt). cp.async double-buffered.
// ---------------------------------------------------------------------------
static constexpr int FS = 72;                         // halves per smem row
static constexpr int FBUF = 64 * FS;
static constexpr int FL_SMEM = 4 * FBUF * 2;          // 36864 B

__global__ __launch_bounds__(128, 3) void flash7(
    const __half* __restrict__ Qg, const __half* __restrict__ Kg,
    const __half* __restrict__ Vt, __half* __restrict__ Og)
{
    extern __shared__ __half fsm[];
    __half* Ksb = fsm;                // [2][64][72]
    __half* Vsb = fsm + 2 * FBUF;     // [2][64][72]

    const int tid = threadIdx.x;
    const int w   = tid >> 5;
    const int l   = tid & 31;
    const int g   = l >> 2;
    const int qd  = l & 3;
    const int b = blockIdx.z, h = blockIdx.y;
    const int q0 = blockIdx.x * 64;

    const uint32_t ksb_s = smem_u32(Ksb);
    const uint32_t vsb_s = smem_u32(Vsb);

    // ldmatrix per-lane offsets (halves)
    const int a_m = (l & 7) + ((l >> 3) & 1) * 8;
    const int a_k = (l >> 4) * 8;
    const int b_n = (l & 7) + (l >> 4) * 8;
    const int b_k = ((l >> 3) & 1) * 8;

    // ---- Stage Q (x0.125) into Ksb[0]; pull frags via ldmatrix
    {
        const __half2 hs = __float2half2_rn(0.125f);
        #pragma unroll
        for (int r = 0; r < 4; r++) {
            int idx = tid + r * 128;
            int row = idx >> 3, c8 = (idx & 7) * 8;
            uint4 v = *(const uint4*)(Qg + (long)(b * SEQ + q0 + row) * DMODEL + h * DHEAD + c8);
            __half2* d = (__half2*)&Ksb[row * FS + c8];
            d[0] = __hmul2(*(__half2*)&v.x, hs);
            d[1] = __hmul2(*(__half2*)&v.y, hs);
            d[2] = __hmul2(*(__half2*)&v.z, hs);
            d[3] = __hmul2(*(__half2*)&v.w, hs);
        }
    }
    __syncthreads();

    uint32_t qa[4][4];   // 4 k-steps over d=64
    #pragma unroll
    for (int ks = 0; ks < 4; ks++)
        ldsm4(qa[ks][0], qa[ks][1], qa[ks][2], qa[ks][3],
              ksb_s + ((w * 16 + a_m) * FS + ks * 16 + a_k) * 2);
    __syncthreads();   // Q-frag reads done before cp.async overwrites buf 0

    float oacc[8][4];
    #pragma unroll
    for (int n = 0; n < 8; n++)
        #pragma unroll
        for (int e = 0; e < 4; e++) oacc[n][e] = 0.0f;
    float m0 = -1e30f, m1 = -1e30f, l0 = 0.0f, l1 = 0.0f;

    const int ntiles = blockIdx.x + 1;
    const long kq_base = (long)b * SEQ * DMODEL + h * DHEAD;       // K: [row][d]
    const long vt_base = (long)h * DHEAD * MROWS + (long)b * SEQ;  // Vt: [d][row]

    auto load_tile = [&](int t, int buf) {
        __half* Kb = Ksb + buf * FBUF;
        __half* Vb = Vsb + buf * FBUF;
        const long koff = kq_base + (long)t * 64 * DMODEL;
        const long voff = vt_base + (long)t * 64;
        #pragma unroll
        for (int r = 0; r < 4; r++) {
            int idx = tid + r * 128;
            int row = idx >> 3, c8 = (idx & 7) * 8;
            cp16(&Kb[row * FS + c8], Kg + koff + (long)row * DMODEL + c8);
            cp16(&Vb[row * FS + c8], Vt + voff + (long)row * MROWS + c8);
        }
        cp_commit();
    };

    load_tile(0, 0);

    for (int t = 0; t < ntiles; t++) {
        const int cur = t & 1;
        if (t + 1 < ntiles) {
            load_tile(t + 1, cur ^ 1);
            cp_wait<1>();
        } else {
            cp_wait<0>();
        }
        __syncthreads();

        const uint32_t ks_s = ksb_s + cur * FBUF * 2;
        const uint32_t vs_s = vsb_s + cur * FBUF * 2;

        // ---- S = Q * K^T : per ks, ldsm all 8 n-tiles (4 x4-loads)
        float sacc[8][4];
        #pragma unroll
        for (int n = 0; n < 8; n++)
            sacc[n][0] = sacc[n][1] = sacc[n][2] = sacc[n][3] = 0.0f;
        #pragma unroll
        for (int ks = 0; ks < 4; ks++) {
            uint32_t kf[8][2];
            #pragma unroll
            for (int p = 0; p < 4; p++)
                ldsm4(kf[2 * p][0], kf[2 * p][1], kf[2 * p + 1][0], kf[2 * p + 1][1],
                      ks_s + ((p * 16 + b_n) * FS + ks * 16 + b_k) * 2);
            #pragma unroll
            for (int n = 0; n < 8; n++)
                mma16(sacc[n][0], sacc[n][1], sacc[n][2], sacc[n][3],
                      qa[ks][0], qa[ks][1], qa[ks][2], qa[ks][3],
                      kf[n][0], kf[n][1]);
        }

        // ---- causal mask (diagonal tile only)
        if (t == ntiles - 1) {
            const int r0 = w * 16 + g, r1 = r0 + 8;
            #pragma unroll
            for (int n = 0; n < 8; n++) {
                int c0 = n * 8 + 2 * qd, c1 = c0 + 1;
                if (c0 > r0) sacc[n][0] = -1e30f;
                if (c1 > r0) sacc[n][1] = -1e30f;
                if (c0 > r1) sacc[n][2] = -1e30f;
                if (c1 > r1) sacc[n][3] = -1e30f;
            }
        }

        // ---- online softmax in registers
        float mx0 = -1e30f, mx1 = -1e30f;
        #pragma unroll
        for (int n = 0; n < 8; n++) {
            mx0 = fmaxf(mx0, fmaxf(sacc[n][0], sacc[n][1]));
            mx1 = fmaxf(mx1, fmaxf(sacc[n][2], sacc[n][3]));
        }
        mx0 = fmaxf(mx0, __shfl_xor_sync(0xffffffffu, mx0, 1));
        mx0 = fmaxf(mx0, __shfl_xor_sync(0xffffffffu, mx0, 2));
        mx1 = fmaxf(mx1, __shfl_xor_sync(0xffffffffu, mx1, 1));
        mx1 = fmaxf(mx1, __shfl_xor_sync(0xffffffffu, mx1, 2));
        const float mn0 = fmaxf(m0, mx0);
        const float mn1 = fmaxf(m1, mx1);
        const float cr0 = __expf(m0 - mn0);
        const float cr1 = __expf(m1 - mn1);

        uint32_t pp0[8], pp1[8];
        float s0 = 0.0f, s1 = 0.0f;
        #pragma unroll
        for (int n = 0; n < 8; n++) {
            float p0 = __expf(sacc[n][0] - mn0);
            float p1 = __expf(sacc[n][1] - mn0);
            float p2 = __expf(sacc[n][2] - mn1);
            float p3 = __expf(sacc[n][3] - mn1);
            s0 += p0 + p1;
            s1 += p2 + p3;
            pp0[n] = packh2(p0, p1);
            pp1[n] = packh2(p2, p3);
        }
        s0 += __shfl_xor_sync(0xffffffffu, s0, 1);
        s0 += __shfl_xor_sync(0xffffffffu, s0, 2);
        s1 += __shfl_xor_sync(0xffffffffu, s1, 1);
        s1 += __shfl_xor_sync(0xffffffffu, s1, 2);
        l0 = l0 * cr0 + s0;
        l1 = l1 * cr1 + s1;
        m0 = mn0;
        m1 = mn1;

        #pragma unroll
        for (int n = 0; n < 8; n++) {
            oacc[n][0] *= cr0; oacc[n][1] *= cr0;
            oacc[n][2] *= cr1; oacc[n][3] *= cr1;
        }

        // ---- O += P * V  (P regs; V^T frags via ldsm; n-tiles = d blocks)
        #pragma unroll
        for (int ks = 0; ks < 4; ks++) {
            const uint32_t a0 = pp0[2 * ks],     a1 = pp1[2 * ks];
            const uint32_t a2 = pp0[2 * ks + 1], a3 = pp1[2 * ks + 1];
            uint32_t vf[8][2];
            #pragma unroll
            for (int p = 0; p < 4; p++)
                ldsm4(vf[2 * p][0], vf[2 * p][1], vf[2 * p + 1][0], vf[2 * p + 1][1],
                      vs_s + ((p * 16 + b_n) * FS + ks * 16 + b_k) * 2);
            #pragma unroll
            for (int n = 0; n < 8; n++)
                mma16(oacc[n][0], oacc[n][1], oacc[n][2], oacc[n][3],
                      a0, a1, a2, a3, vf[n][0], vf[n][1]);
        }
        __syncthreads();
    }

    // ---- epilogue: normalize, write fp16
    const float inv0 = 1.0f / l0;
    const float inv1 = 1.0f / l1;
    const long row0 = (long)(b * SEQ + q0 + w * 16 + g);
    const long row1 = row0 + 8;
    #pragma unroll
    for (int n = 0; n < 8; n++) {
        int c = h * DHEAD + n * 8 + 2 * qd;
        *(uint32_t*)(Og + row0 * DMODEL + c) = packh2(oacc[n][0] * inv0, oacc[n][1] * inv0);
        *(uint32_t*)(Og + row1 * DMODEL + c) = packh2(oacc[n][2] * inv1, oacc[n][3] * inv1);
    }
}

// ---------------------------------------------------------------------------
// Launch
// ---------------------------------------------------------------------------
extern "C" void kernel_launch(void* const* d_in, const int* in_sizes, int n_in,
                              void* d_out, int out_size)
{
    const float* x  = (const float*)d_in[0];
    const float* wq = (const float*)d_in[1];
    const float* wk = (const float*)d_in[2];
    const float* wv = (const float*)d_in[3];
    const float* wo = (const float*)d_in[4];
    float* out = (float*)d_out;

    __half *qb, *kb, *vb, *vtb, *ab, *xh, *wh;
    cudaGetSymbolAddress((void**)&qb,  g_q);
    cudaGetSymbolAddress((void**)&kb,  g_k);
    cudaGetSymbolAddress((void**)&vb,  g_v);
    cudaGetSymbolAddress((void**)&vtb, g_vt);
    cudaGetSymbolAddress((void**)&ab,  g_att);
    cudaGetSymbolAddress((void**)&xh,  g_xh);
    cudaGetSymbolAddress((void**)&wh,  g_wh);

    __half* wqt = wh;
    __half* wkt = wh + (size_t)DMODEL * DMODEL;
    __half* wvt = wh + 2 * (size_t)DMODEL * DMODEL;
    __half* wot = wh + 3 * (size_t)DMODEL * DMODEL;

    // Pre-passes
    const int NX4 = MROWS * DMODEL / 4;
    f32_to_f16<<<(NX4 + 255) / 256, 256>>>(x, xh, NX4);
    dim3 tg(DMODEL / 32, DMODEL / 32, 4);
    transpose_w4<<<tg, 256>>>(wq, wk, wv, wo, wqt, wkt, wvt, wot);

    cudaFuncSetAttribute((const void*)gemm_h<3, true>,  cudaFuncAttributeMaxDynamicSharedMemorySize, GEMM_SMEM);
    cudaFuncSetAttribute((const void*)gemm_h<1, false>, cudaFuncAttributeMaxDynamicSharedMemorySize, GEMM_SMEM);

    // Fused QKV projection (fp16 out)
    dim3 gq(DMODEL / 128, MROWS / 128, 3);   // (8, 64, 3)
    gemm_h<3, true><<<gq, 256, GEMM_SMEM>>>(xh, wqt, wkt, wvt, qb, kb, vb);

    // V transpose for PV B-operand
    dim3 vg(DMODEL / 64, MROWS / 64);        // (16, 128)
    transpose_v<<<vg, 256>>>(vb, vtb);

    cudaFuncSetAttribute(flash7, cudaFuncAttributeMaxDynamicSharedMemorySize, FL_SMEM);
    dim3 fg(SEQ / 64, NHEAD, BATCH);         // (32, 16, 4)
    flash7<<<fg, 128, FL_SMEM>>>(qb, kb, vtb, ab);

    // Output projection (fp32 out)
    dim3 go(DMODEL / 128, MROWS / 128, 1);   // (8, 64)
    gemm_h<1, false><<<go, 256, GEMM_SMEM>>>(ab, wot, nullptr, nullptr, out, nullptr, nullptr);
}

// round 11
// speedup vs baseline: 8.5697x; 1.0742x over previous
#include <cuda_runtime.h>
#include <cuda_fp16.h>
#include <cstddef>
#include <cstdint>

// Problem constants
static constexpr int BATCH  = 4;
static constexpr int SEQ    = 2048;
static constexpr int DMODEL = 1024;
static constexpr int NHEAD  = 16;
static constexpr int DHEAD  = 64;
static constexpr int MROWS  = BATCH * SEQ;   // 8192

// Scratch (device globals). All activations fp16.
__device__ __half g_q[MROWS * DMODEL];
__device__ __half g_k[MROWS * DMODEL];
__device__ __half g_v[MROWS * DMODEL];
__device__ __half g_att[MROWS * DMODEL];
__device__ __half g_xh[MROWS * DMODEL];         // fp16 x
__device__ __half g_wh[4 * DMODEL * DMODEL];    // fp16 W^T (Q,K,V,O), [N][K]

// ---------------- helpers ----------------
__device__ __forceinline__ uint32_t smem_u32(const void* p) {
    return (uint32_t)__cvta_generic_to_shared(p);
}
__device__ __forceinline__ void cp16s(uint32_t smem_dst, const void* gsrc) {
    asm volatile("cp.async.cg.shared.global [%0], [%1], 16;\n" :: "r"(smem_dst), "l"(gsrc));
}
__device__ __forceinline__ void cp16(void* smem_dst, const void* gsrc) {
    cp16s(smem_u32(smem_dst), gsrc);
}
__device__ __forceinline__ void cp_commit() { asm volatile("cp.async.commit_group;\n"); }
template <int N>
__device__ __forceinline__ void cp_wait() { asm volatile("cp.async.wait_group %0;\n" :: "n"(N)); }

// mma.m16n8k16 fp16 in, fp32 accumulate. row.col.
__device__ __forceinline__ void mma16(float& c0, float& c1, float& c2, float& c3,
                                      uint32_t a0, uint32_t a1, uint32_t a2, uint32_t a3,
                                      uint32_t b0, uint32_t b1)
{
    asm volatile(
        "mma.sync.aligned.m16n8k16.row.col.f32.f16.f16.f32 "
        "{%0,%1,%2,%3}, {%4,%5,%6,%7}, {%8,%9}, {%0,%1,%2,%3};\n"
        : "+f"(c0), "+f"(c1), "+f"(c2), "+f"(c3)
        : "r"(a0), "r"(a1), "r"(a2), "r"(a3), "r"(b0), "r"(b1));
}

// ldmatrix x4 (non-transposed / transposed)
__device__ __forceinline__ void ldsm4(uint32_t& r0, uint32_t& r1, uint32_t& r2, uint32_t& r3,
                                      uint32_t saddr)
{
    asm volatile("ldmatrix.sync.aligned.m8n8.x4.shared.b16 {%0,%1,%2,%3}, [%4];"
                 : "=r"(r0), "=r"(r1), "=r"(r2), "=r"(r3) : "r"(saddr));
}
__device__ __forceinline__ void ldsm4t(uint32_t& r0, uint32_t& r1, uint32_t& r2, uint32_t& r3,
                                       uint32_t saddr)
{
    asm volatile("ldmatrix.sync.aligned.m8n8.x4.trans.shared.b16 {%0,%1,%2,%3}, [%4];"
                 : "=r"(r0), "=r"(r1), "=r"(r2), "=r"(r3) : "r"(saddr));
}

__device__ __forceinline__ uint32_t packh2(float a, float b) {
    __half2 h = __floats2half2_rn(a, b);
    return *(uint32_t*)&h;
}

// ---------------------------------------------------------------------------
// fp32 -> fp16 elementwise
// ---------------------------------------------------------------------------
__global__ __launch_bounds__(256) void f32_to_f16(const float* __restrict__ in,
                                                  __half* __restrict__ out, int n4)
{
    int i = blockIdx.x * 256 + threadIdx.x;
    if (i < n4) {
        float4 v = ((const float4*)in)[i];
        uint2 u;
        u.x = packh2(v.x, v.y);
        u.y = packh2(v.z, v.w);
        ((uint2*)out)[i] = u;
    }
}

// ---------------------------------------------------------------------------
// Fused: transpose + fp16-round all four 1024x1024 weights (grid.z selects).
// ---------------------------------------------------------------------------
__global__ __launch_bounds__(256) void transpose_w4(
    const float* __restrict__ w0, const float* __restrict__ w1,
    const float* __restrict__ w2, const float* __restrict__ w3,
    __half* __restrict__ o0, __half* __restrict__ o1,
    __half* __restrict__ o2, __half* __restrict__ o3)
{
    const float* in = w0; __half* out = o0;
    if (blockIdx.z == 1) { in = w1; out = o1; }
    else if (blockIdx.z == 2) { in = w2; out = o2; }
    else if (blockIdx.z == 3) { in = w3; out = o3; }

    __shared__ float t[32][33];
    const int bx = blockIdx.x * 32, by = blockIdx.y * 32;
    const int tx = threadIdx.x & 31, ty = threadIdx.x >> 5;
    #pragma unroll
    for (int j = 0; j < 32; j += 8)
        t[ty + j][tx] = in[(long)(by + ty + j) * DMODEL + bx + tx];
    __syncthreads();
    #pragma unroll
    for (int j = 0; j < 32; j += 8)
        out[(long)(bx + ty + j) * DMODEL + by + tx] = __float2half_rn(t[tx][ty + j]);
}

// ---------------------------------------------------------------------------
// fp16 GEMM, 64x64 warp tiles. C = A[M,K] * Bt[N,K]^T, fp32 accum.
// 128x128x32 CTA tile, 128 thr = 4 warps. ldmatrix frag loads, stride 40.
// cp.async double-buffered.
// ---------------------------------------------------------------------------
static constexpr int HS = 40;                       // halves per smem row
static constexpr int HBUF = 128 * HS;               // halves per buffer
static constexpr int GEMM_SMEM = 4 * HBUF * 2;      // 40960 B

template <int NMAT, bool OUT_HALF>
__global__ __launch_bounds__(128, 2) void gemm_h(
    const __half* __restrict__ A,
    const __half* __restrict__ B0, const __half* __restrict__ B1, const __half* __restrict__ B2,
    void* __restrict__ C0, void* __restrict__ C1, void* __restrict__ C2)
{
    extern __shared__ __half hsm[];
    __half* As = hsm;                 // [2][128][40]
    __half* Bs = hsm + 2 * HBUF;      // [2][128][40]

    const __half* Bt = B0;
    void* C = C0;
    if (NMAT > 1) {
        if (blockIdx.z == 1) { Bt = B1; C = C1; }
        else if (blockIdx.z == 2) { Bt = B2; C = C2; }
    }

    const int tid = threadIdx.x;
    const int wid = tid >> 5;
    const int l   = tid & 31;
    const int g   = l >> 2;
    const int qd  = l & 3;
    const int wm  = (wid & 1) * 64;
    const int wn  = (wid >> 1) * 64;
    const long bm0 = (long)blockIdx.y * 128;
    const long bn0 = (long)blockIdx.x * 128;

    // ldmatrix per-lane offsets (in halves)
    const int a_m = (l & 7) + ((l >> 3) & 1) * 8;
    const int a_k = (l >> 4) * 8;
    const int b_n = (l & 7) + (l >> 4) * 8;
    const int b_k = ((l >> 3) & 1) * 8;

    float acc[4][8][4];
    #pragma unroll
    for (int i = 0; i < 4; i++)
        #pragma unroll
        for (int j = 0; j < 8; j++)
            #pragma unroll
            for (int e = 0; e < 4; e++) acc[i][j][e] = 0.0f;

    const uint32_t asb = smem_u32(As);
    const uint32_t bsb = smem_u32(Bs);

    // chunk loader: A/B each 128 rows x 32 halves (64B = 4 x 16B) -> 4 cp16/thr each
    auto load_chunk = [&](int k0, int buf) {
        const uint32_t ab = asb + buf * HBUF * 2;
        const uint32_t bb = bsb + buf * HBUF * 2;
        #pragma unroll
        for (int i = 0; i < 4; i++) {
            int idx = tid + i * 128;
            int row = idx >> 2, ci = idx & 3;
            cp16s(ab + row * (HS * 2) + ci * 16, A  + (bm0 + row) * DMODEL + k0 + ci * 8);
            cp16s(bb + row * (HS * 2) + ci * 16, Bt + (bn0 + row) * DMODEL + k0 + ci * 8);
        }
        cp_commit();
    };

    load_chunk(0, 0);
    cp_wait<0>();
    __syncthreads();

    int cur = 0;
    for (int k0 = 32; k0 <= DMODEL; k0 += 32) {
        const bool more = (k0 < DMODEL);
        if (more) load_chunk(k0, cur ^ 1);

        const uint32_t acb = asb + cur * HBUF * 2;
        const uint32_t bcb = bsb + cur * HBUF * 2;
        #pragma unroll
        for (int ks = 0; ks < 2; ks++) {
            const int kb0 = ks * 16;
            uint32_t af[4][4];
            #pragma unroll
            for (int tm = 0; tm < 4; tm++)
                ldsm4(af[tm][0], af[tm][1], af[tm][2], af[tm][3],
                      acb + ((wm + tm * 16 + a_m) * HS + kb0 + a_k) * 2);
            uint32_t bf[8][2];
            #pragma unroll
            for (int tp = 0; tp < 4; tp++)
                ldsm4(bf[2 * tp][0], bf[2 * tp][1], bf[2 * tp + 1][0], bf[2 * tp + 1][1],
                      bcb + ((wn + tp * 16 + b_n) * HS + kb0 + b_k) * 2);
            #pragma unroll
            for (int tm = 0; tm < 4; tm++)
                #pragma unroll
                for (int tn = 0; tn < 8; tn++)
                    mma16(acc[tm][tn][0], acc[tm][tn][1], acc[tm][tn][2], acc[tm][tn][3],
                          af[tm][0], af[tm][1], af[tm][2], af[tm][3],
                          bf[tn][0], bf[tn][1]);
        }

        if (more) {
            cp_wait<0>();
            __syncthreads();
            cur ^= 1;
        }
    }

    // epilogue
    #pragma unroll
    for (int tm = 0; tm < 4; tm++) {
        const long row0 = bm0 + wm + tm * 16 + g;
        const long row1 = row0 + 8;
        #pragma unroll
        for (int tn = 0; tn < 8; tn++) {
            const long col = bn0 + wn + tn * 8 + 2 * qd;
            if (OUT_HALF) {
                __half* Ch = (__half*)C;
                *(uint32_t*)(Ch + row0 * DMODEL + col) = packh2(acc[tm][tn][0], acc[tm][tn][1]);
                *(uint32_t*)(Ch + row1 * DMODEL + col) = packh2(acc[tm][tn][2], acc[tm][tn][3]);
            } else {
                float* Cf = (float*)C;
                *(float2*)(Cf + row0 * DMODEL + col) = make_float2(acc[tm][tn][0], acc[tm][tn][1]);
                *(float2*)(Cf + row1 * DMODEL + col) = make_float2(acc[tm][tn][2], acc[tm][tn][3]);
            }
        }
    }
}

// ---------------------------------------------------------------------------
// Flash attention fp16 (causal). K AND V both [key][d] in smem; V fragments
// produced by ldmatrix.trans (no pre-transpose). P in registers. cp.async
// double-buffered.
// ---------------------------------------------------------------------------
static constexpr int FS = 72;                         // halves per smem row
static constexpr int FBUF = 64 * FS;
static constexpr int FL_SMEM = 4 * FBUF * 2;          // 36864 B

__global__ __launch_bounds__(128, 3) void flash8(
    const __half* __restrict__ Qg, const __half* __restrict__ Kg,
    const __half* __restrict__ Vg, __half* __restrict__ Og)
{
    extern __shared__ __half fsm[];
    __half* Ksb = fsm;                // [2][64][72]
    __half* Vsb = fsm + 2 * FBUF;     // [2][64][72]

    const int tid = threadIdx.x;
    const int w   = tid >> 5;
    const int l   = tid & 31;
    const int g   = l >> 2;
    const int qd  = l & 3;
    const int b = blockIdx.z, h = blockIdx.y;
    const int q0 = blockIdx.x * 64;

    const uint32_t ksb_s = smem_u32(Ksb);
    const uint32_t vsb_s = smem_u32(Vsb);

    // ldmatrix per-lane offsets (halves)
    const int a_m = (l & 7) + ((l >> 3) & 1) * 8;
    const int a_k = (l >> 4) * 8;
    const int b_n = (l & 7) + (l >> 4) * 8;
    const int b_k = ((l >> 3) & 1) * 8;
    // trans (V): lanes 0-15 -> key rows 0-15 of block, lanes 16-31 -> d +8
    const int v_r = l & 15;
    const int v_c = (l >> 4) * 8;

    // ---- Stage Q (x0.125) into Ksb[0]; pull frags via ldmatrix
    {
        const __half2 hs = __float2half2_rn(0.125f);
        #pragma unroll
        for (int r = 0; r < 4; r++) {
            int idx = tid + r * 128;
            int row = idx >> 3, c8 = (idx & 7) * 8;
            uint4 v = *(const uint4*)(Qg + (long)(b * SEQ + q0 + row) * DMODEL + h * DHEAD + c8);
            __half2* d = (__half2*)&Ksb[row * FS + c8];
            d[0] = __hmul2(*(__half2*)&v.x, hs);
            d[1] = __hmul2(*(__half2*)&v.y, hs);
            d[2] = __hmul2(*(__half2*)&v.z, hs);
            d[3] = __hmul2(*(__half2*)&v.w, hs);
        }
    }
    __syncthreads();

    uint32_t qa[4][4];   // 4 k-steps over d=64
    #pragma unroll
    for (int ks = 0; ks < 4; ks++)
        ldsm4(qa[ks][0], qa[ks][1], qa[ks][2], qa[ks][3],
              ksb_s + ((w * 16 + a_m) * FS + ks * 16 + a_k) * 2);
    __syncthreads();   // Q-frag reads done before cp.async overwrites buf 0

    float oacc[8][4];
    #pragma unroll
    for (int n = 0; n < 8; n++)
        #pragma unroll
        for (int e = 0; e < 4; e++) oacc[n][e] = 0.0f;
    float m0 = -1e30f, m1 = -1e30f, l0 = 0.0f, l1 = 0.0f;

    const int ntiles = blockIdx.x + 1;
    const long bh_base = (long)b * SEQ * DMODEL + h * DHEAD;   // K/V: [row][d]

    auto load_tile = [&](int t, int buf) {
        __half* Kb = Ksb + buf * FBUF;
        __half* Vb = Vsb + buf * FBUF;
        const long off = bh_base + (long)t * 64 * DMODEL;
        #pragma unroll
        for (int r = 0; r < 4; r++) {
            int idx = tid + r * 128;
            int row = idx >> 3, c8 = (idx & 7) * 8;
            cp16(&Kb[row * FS + c8], Kg + off + (long)row * DMODEL + c8);
            cp16(&Vb[row * FS + c8], Vg + off + (long)row * DMODEL + c8);
        }
        cp_commit();
    };

    load_tile(0, 0);

    for (int t = 0; t < ntiles; t++) {
        const int cur = t & 1;
        if (t + 1 < ntiles) {
            load_tile(t + 1, cur ^ 1);
            cp_wait<1>();
        } else {
            cp_wait<0>();
        }
        __syncthreads();

        const uint32_t ks_s = ksb_s + cur * FBUF * 2;
        const uint32_t vs_s = vsb_s + cur * FBUF * 2;

        // ---- S = Q * K^T
        float sacc[8][4];
        #pragma unroll
        for (int n = 0; n < 8; n++)
            sacc[n][0] = sacc[n][1] = sacc[n][2] = sacc[n][3] = 0.0f;
        #pragma unroll
        for (int ks = 0; ks < 4; ks++) {
            uint32_t kf[8][2];
            #pragma unroll
            for (int p = 0; p < 4; p++)
                ldsm4(kf[2 * p][0], kf[2 * p][1], kf[2 * p + 1][0], kf[2 * p + 1][1],
                      ks_s + ((p * 16 + b_n) * FS + ks * 16 + b_k) * 2);
            #pragma unroll
            for (int n = 0; n < 8; n++)
                mma16(sacc[n][0], sacc[n][1], sacc[n][2], sacc[n][3],
                      qa[ks][0], qa[ks][1], qa[ks][2], qa[ks][3],
                      kf[n][0], kf[n][1]);
        }

        // ---- causal mask (diagonal tile only)
        if (t == ntiles - 1) {
            const int r0 = w * 16 + g, r1 = r0 + 8;
            #pragma unroll
            for (int n = 0; n < 8; n++) {
                int c0 = n * 8 + 2 * qd, c1 = c0 + 1;
                if (c0 > r0) sacc[n][0] = -1e30f;
                if (c1 > r0) sacc[n][1] = -1e30f;
                if (c0 > r1) sacc[n][2] = -1e30f;
                if (c1 > r1) sacc[n][3] = -1e30f;
            }
        }

        // ---- online softmax in registers
        float mx0 = -1e30f, mx1 = -1e30f;
        #pragma unroll
        for (int n = 0; n < 8; n++) {
            mx0 = fmaxf(mx0, fmaxf(sacc[n][0], sacc[n][1]));
            mx1 = fmaxf(mx1, fmaxf(sacc[n][2], sacc[n][3]));
        }
        mx0 = fmaxf(mx0, __shfl_xor_sync(0xffffffffu, mx0, 1));
        mx0 = fmaxf(mx0, __shfl_xor_sync(0xffffffffu, mx0, 2));
        mx1 = fmaxf(mx1, __shfl_xor_sync(0xffffffffu, mx1, 1));
        mx1 = fmaxf(mx1, __shfl_xor_sync(0xffffffffu, mx1, 2));
        const float mn0 = fmaxf(m0, mx0);
        const float mn1 = fmaxf(m1, mx1);
        const float cr0 = __expf(m0 - mn0);
        const float cr1 = __expf(m1 - mn1);

        uint32_t pp0[8], pp1[8];
        float s0 = 0.0f, s1 = 0.0f;
        #pragma unroll
        for (int n = 0; n < 8; n++) {
            float p0 = __expf(sacc[n][0] - mn0);
            float p1 = __expf(sacc[n][1] - mn0);
            float p2 = __expf(sacc[n][2] - mn1);
            float p3 = __expf(sacc[n][3] - mn1);
            s0 += p0 + p1;
            s1 += p2 + p3;
            pp0[n] = packh2(p0, p1);
            pp1[n] = packh2(p2, p3);
        }
        s0 += __shfl_xor_sync(0xffffffffu, s0, 1);
        s0 += __shfl_xor_sync(0xffffffffu, s0, 2);
        s1 += __shfl_xor_sync(0xffffffffu, s1, 1);
        s1 += __shfl_xor_sync(0xffffffffu, s1, 2);
        l0 = l0 * cr0 + s0;
        l1 = l1 * cr1 + s1;
        m0 = mn0;
        m1 = mn1;

        #pragma unroll
        for (int n = 0; n < 8; n++) {
            oacc[n][0] *= cr0; oacc[n][1] *= cr0;
            oacc[n][2] *= cr1; oacc[n][3] *= cr1;
        }

        // ---- O += P * V  (P regs; V^T frags via ldmatrix.trans of [key][d])
        #pragma unroll
        for (int ks = 0; ks < 4; ks++) {
            const uint32_t a0 = pp0[2 * ks],     a1 = pp1[2 * ks];
            const uint32_t a2 = pp0[2 * ks + 1], a3 = pp1[2 * ks + 1];
            #pragma unroll
            for (int p = 0; p < 4; p++) {
                uint32_t v0, v1, v2, v3;   // b0/b1 for d-tiles 2p, 2p+1
                ldsm4t(v0, v1, v2, v3,
                       vs_s + ((ks * 16 + v_r) * FS + p * 16 + v_c) * 2);
                mma16(oacc[2 * p][0], oacc[2 * p][1], oacc[2 * p][2], oacc[2 * p][3],
                      a0, a1, a2, a3, v0, v1);
                mma16(oacc[2 * p + 1][0], oacc[2 * p + 1][1], oacc[2 * p + 1][2], oacc[2 * p + 1][3],
                      a0, a1, a2, a3, v2, v3);
            }
        }
        __syncthreads();
    }

    // ---- epilogue: normalize, write fp16
    const float inv0 = 1.0f / l0;
    const float inv1 = 1.0f / l1;
    const long row0 = (long)(b * SEQ + q0 + w * 16 + g);
    const long row1 = row0 + 8;
    #pragma unroll
    for (int n = 0; n < 8; n++) {
        int c = h * DHEAD + n * 8 + 2 * qd;
        *(uint32_t*)(Og + row0 * DMODEL + c) = packh2(oacc[n][0] * inv0, oacc[n][1] * inv0);
        *(uint32_t*)(Og + row1 * DMODEL + c) = packh2(oacc[n][2] * inv1, oacc[n][3] * inv1);
    }
}

// ---------------------------------------------------------------------------
// Launch
// ---------------------------------------------------------------------------
extern "C" void kernel_launch(void* const* d_in, const int* in_sizes, int n_in,
                              void* d_out, int out_size)
{
    const float* x  = (const float*)d_in[0];
    const float* wq = (const float*)d_in[1];
    const float* wk = (const float*)d_in[2];
    const float* wv = (const float*)d_in[3];
    const float* wo = (const float*)d_in[4];
    float* out = (float*)d_out;

    __half *qb, *kb, *vb, *ab, *xh, *wh;
    cudaGetSymbolAddress((void**)&qb, g_q);
    cudaGetSymbolAddress((void**)&kb, g_k);
    cudaGetSymbolAddress((void**)&vb, g_v);
    cudaGetSymbolAddress((void**)&ab, g_att);
    cudaGetSymbolAddress((void**)&xh, g_xh);
    cudaGetSymbolAddress((void**)&wh, g_wh);

    __half* wqt = wh;
    __half* wkt = wh + (size_t)DMODEL * DMODEL;
    __half* wvt = wh + 2 * (size_t)DMODEL * DMODEL;
    __half* wot = wh + 3 * (size_t)DMODEL * DMODEL;

    // Pre-passes
    const int NX4 = MROWS * DMODEL / 4;
    f32_to_f16<<<(NX4 + 255) / 256, 256>>>(x, xh, NX4);
    dim3 tg(DMODEL / 32, DMODEL / 32, 4);
    transpose_w4<<<tg, 256>>>(wq, wk, wv, wo, wqt, wkt, wvt, wot);

    cudaFuncSetAttribute((const void*)gemm_h<3, true>,  cudaFuncAttributeMaxDynamicSharedMemorySize, GEMM_SMEM);
    cudaFuncSetAttribute((const void*)gemm_h<1, false>, cudaFuncAttributeMaxDynamicSharedMemorySize, GEMM_SMEM);

    // Fused QKV projection (fp16 out)
    dim3 gq(DMODEL / 128, MROWS / 128, 3);   // (8, 64, 3)
    gemm_h<3, true><<<gq, 128, GEMM_SMEM>>>(xh, wqt, wkt, wvt, qb, kb, vb);

    cudaFuncSetAttribute(flash8, cudaFuncAttributeMaxDynamicSharedMemorySize, FL_SMEM);
    dim3 fg(SEQ / 64, NHEAD, BATCH);         // (32, 16, 4)
    flash8<<<fg, 128, FL_SMEM>>>(qb, kb, vb, ab);

    // Output projection (fp32 out)
    dim3 go(DMODEL / 128, MROWS / 128, 1);   // (8, 64)
    gemm_h<1, false><<<go, 128, GEMM_SMEM>>>(ab, wot, nullptr, nullptr, out, nullptr, nullptr);
}